// round 3
// baseline (speedup 1.0000x reference)
#include <cuda_runtime.h>

constexpr int NB = 8, NE = 64, NCIN = 128, NC = 128, NPRE = 128;

__device__ __forceinline__ float leaky(float v) { return v >= 0.f ? v : 0.1f * v; }

// scratch (static device globals; no allocation)
__device__ float d_xf[NB * NC * NE];
__device__ float d_yf[NB * NC * NE];
__device__ float d_L[NB * NE * NE];
__device__ float d_pltype[20];
__device__ float d_eltype[10];
__device__ float d_pathfea[NB * 2 * NC * NE * NE];
__device__ float d_h[NB * NC * NE * NE];
__device__ float d_g[NB * NE * NE];
__device__ float d_xlin[NB * NE * NCIN];
__device__ float d_ylin[NB * NE * NCIN];
__device__ float d_w2t[NC * 9 * NC];

__global__ void k_prep(const float* __restrict__ path_table, const float* __restrict__ pconv_w,
                       const float* __restrict__ edge_table, const float* __restrict__ econv_w) {
    int t = threadIdx.x;
    if (t < 20) {
        float s = 0.f;
        #pragma unroll
        for (int d = 0; d < 32; d++) s += path_table[t * 32 + d] * pconv_w[d];
        d_pltype[t] = leaky(s);
    }
    if (t < 10) {
        float s = 0.f;
        #pragma unroll
        for (int d = 0; d < 32; d++) s += edge_table[t * 32 + d] * econv_w[d];
        d_eltype[t] = leaky(s);
    }
}

__global__ void k_w2t(const float* __restrict__ w2) {
    int idx = blockIdx.x * 256 + threadIdx.x;
    if (idx < NC * NC * 9) {
        int o = idx / (NC * 9);
        int rem = idx % (NC * 9);
        d_w2t[rem * NC + o] = w2[idx];
    }
}

// x_f/y_f: [C,CIN] x [B,CIN,E] -> [B,C,E]
__global__ void k_xfyf(const float* __restrict__ x, const float* __restrict__ y,
                       const float* __restrict__ xw, const float* __restrict__ yw) {
    int c = blockIdx.x, b = blockIdx.y;
    const float* in = blockIdx.z ? y : x;
    const float* w  = blockIdx.z ? yw : xw;
    float* out      = blockIdx.z ? d_yf : d_xf;
    __shared__ float ws[NCIN];
    int m = threadIdx.x;
    for (int i = m; i < NCIN; i += 64) ws[i] = w[c * NCIN + i];
    __syncthreads();
    const float* inb = in + b * NCIN * NE + m;
    float acc = 0.f;
    #pragma unroll 8
    for (int i = 0; i < NCIN; i++) acc += ws[i] * inb[i * NE];
    out[(b * NC + c) * NE + m] = acc;
}

__global__ void k_selflog(const float* __restrict__ xc2_w, const float* __restrict__ xc2_b,
                          const float* __restrict__ yc2_w, const float* __restrict__ yc2_b) {
    int b = blockIdx.x, t = threadIdx.x;
    __shared__ float xs[NE], yo[NE];
    if (t < 64) {
        float a = 0.f;
        #pragma unroll 8
        for (int c = 0; c < NC; c++) a += xc2_w[c] * d_xf[(b * NC + c) * NE + t];
        xs[t] = a + xc2_b[0];
    } else {
        int m = t - 64;
        float a = 0.f;
        #pragma unroll 8
        for (int c = 0; c < NC; c++) a += yc2_w[c] * d_yf[(b * NC + c) * NE + m];
        yo[m] = a + yc2_b[0];
    }
    __syncthreads();
    for (int idx = t; idx < NE * NE; idx += 128) {
        int p = idx >> 6, q = idx & 63;
        d_L[b * NE * NE + idx] = leaky(xs[q] + yo[p]);
    }
}

// per-(b,e): local, dual softmax, two 128x64x64 GEMMs
__global__ __launch_bounds__(256) void k_attn(const int* __restrict__ path_mat,
                                              const float* __restrict__ p_bias) {
    __shared__ float loc[64 * 65];
    __shared__ float Asm[64 * 65];
    __shared__ float cmax[64], cinv[64];
    int e = blockIdx.x, b = blockIdx.y, t = threadIdx.x;
    const int*   pm = path_mat + (b * NE + e) * 4096;
    const float* pb = p_bias  + (size_t)(b * NE + e) * 4096;
    const float* Lb = d_L + b * 4096;

    for (int idx = t; idx < 4096; idx += 256) {
        int m = idx >> 6, n = idx & 63;
        loc[m * 65 + n] = Lb[idx] + d_pltype[pm[idx]] + pb[idx];
    }
    __syncthreads();

    if (t < 64) {  // row softmax over n
        float mx = -1e30f;
        for (int n = 0; n < 64; n++) mx = fmaxf(mx, loc[t * 65 + n]);
        float s = 0.f;
        for (int n = 0; n < 64; n++) { float ev = __expf(loc[t * 65 + n] - mx); Asm[t * 65 + n] = ev; s += ev; }
        float inv = 1.f / s;
        for (int n = 0; n < 64; n++) Asm[t * 65 + n] *= inv;
    } else if (t < 128) {  // column stats
        int n = t - 64;
        float mx = -1e30f;
        for (int m = 0; m < 64; m++) mx = fmaxf(mx, loc[m * 65 + n]);
        float s = 0.f;
        for (int m = 0; m < 64; m++) s += __expf(loc[m * 65 + n] - mx);
        cmax[n] = mx; cinv[n] = 1.f / s;
    }
    __syncthreads();

    for (int idx = t; idx < 4096; idx += 256) {
        int m = idx >> 6, n = idx & 63;
        loc[m * 65 + n] = __expf(loc[m * 65 + n] - cmax[n]) * cinv[n];
    }
    __syncthreads();

    int c0 = (t >> 4) * 8;
    int m0 = (t & 15) * 4;
    float accx[8][4], accy[8][4];
    #pragma unroll
    for (int u = 0; u < 8; u++)
        #pragma unroll
        for (int v = 0; v < 4; v++) { accx[u][v] = 0.f; accy[u][v] = 0.f; }
    const float* yfb = d_yf + b * NC * NE;
    const float* xfb = d_xf + b * NC * NE;
    for (int k = 0; k < 64; k++) {
        float ax[8], ay[8], bx[4], by[4];
        #pragma unroll
        for (int u = 0; u < 8; u++) {
            ax[u] = yfb[(c0 + u) * NE + k];
            ay[u] = xfb[(c0 + u) * NE + k];
        }
        #pragma unroll
        for (int v = 0; v < 4; v++) {
            bx[v] = Asm[(m0 + v) * 65 + k];
            by[v] = loc[k * 65 + m0 + v];
        }
        #pragma unroll
        for (int u = 0; u < 8; u++)
            #pragma unroll
            for (int v = 0; v < 4; v++) {
                accx[u][v] += ax[u] * bx[v];
                accy[u][v] += ay[u] * by[v];
            }
    }
    #pragma unroll
    for (int u = 0; u < 8; u++) {
        int c = c0 + u;
        #pragma unroll
        for (int v = 0; v < 4; v++) {
            int m = m0 + v;
            d_pathfea[((b * 256 + c) * NE + e) * NE + m]       = leaky(accx[u][v] + xfb[c * NE + m]);
            d_pathfea[((b * 256 + 128 + c) * NE + e) * NE + m] = leaky(accy[u][v] + yfb[c * NE + m]);
        }
    }
}

// conv1 1x1: [128,384] @ [384,4096] per batch
__global__ __launch_bounds__(256) void k_conv1(const float* __restrict__ pre_out,
                                               const float* __restrict__ w1,
                                               const float* __restrict__ b1) {
    __shared__ float as[128 * 33];
    __shared__ float bs[32 * 128];
    int tile = blockIdx.x, b = blockIdx.y, t = threadIdx.x;
    int p0 = tile * 128;
    int og = t >> 4, pg = t & 15;
    int o0 = og * 8;
    float acc[8][8];
    #pragma unroll
    for (int u = 0; u < 8; u++)
        #pragma unroll
        for (int v = 0; v < 8; v++) acc[u][v] = 0.f;

    for (int k0 = 0; k0 < 384; k0 += 32) {
        __syncthreads();
        for (int idx = t; idx < 4096; idx += 256) {
            int o = idx >> 5, kk = idx & 31;
            as[o * 33 + kk] = w1[o * 384 + k0 + kk];
        }
        for (int idx = t; idx < 4096; idx += 256) {
            int kk = idx >> 7, p = idx & 127;
            int c = k0 + kk;
            bs[kk * 128 + p] = (c < 256)
                ? d_pathfea[(b * 256 + c) * 4096 + p0 + p]
                : pre_out[((size_t)b * NPRE + (c - 256)) * 4096 + p0 + p];
        }
        __syncthreads();
        #pragma unroll 4
        for (int kk = 0; kk < 32; kk++) {
            float av[8], bv[8];
            #pragma unroll
            for (int u = 0; u < 8; u++) av[u] = as[(o0 + u) * 33 + kk];
            #pragma unroll
            for (int v = 0; v < 8; v++) bv[v] = bs[kk * 128 + pg + 16 * v];
            #pragma unroll
            for (int u = 0; u < 8; u++)
                #pragma unroll
                for (int v = 0; v < 8; v++) acc[u][v] += av[u] * bv[v];
        }
    }
    #pragma unroll
    for (int u = 0; u < 8; u++) {
        int o = o0 + u;
        float bb = b1[o];
        #pragma unroll
        for (int v = 0; v < 8; v++)
            d_h[(b * NC + o) * 4096 + p0 + pg + 16 * v] = leaky(acc[u][v] + bb);
    }
}

// conv2 3x3 SAME
__global__ __launch_bounds__(256) void k_conv2(const float* __restrict__ b2,
                                               float* __restrict__ out) {
    __shared__ __align__(16) float hs[8 * 208];
    __shared__ __align__(16) float ws[8 * 9 * 128];
    int i = blockIdx.x, b = blockIdx.y, t = threadIdx.x;
    int og = t >> 4, jg = t & 15;
    int o0 = og * 8, j0 = jg * 4;
    float acc[8][4];
    #pragma unroll
    for (int u = 0; u < 8; u++)
        #pragma unroll
        for (int v = 0; v < 4; v++) acc[u][v] = 0.f;

    for (int c0 = 0; c0 < 128; c0 += 8) {
        __syncthreads();
        for (int idx = t; idx < 8 * 204; idx += 256) {
            int cc = idx / 204, rem = idx % 204;
            int r = rem / 68, jp = rem % 68;
            int row = i + r - 1;
            float v = 0.f;
            if (jp >= 1 && jp <= 64 && row >= 0 && row < 64)
                v = d_h[((b * NC + c0 + cc) * 64 + row) * 64 + (jp - 1)];
            hs[cc * 208 + r * 68 + jp] = v;
        }
        for (int idx = t; idx < 9216; idx += 256)
            ws[idx] = d_w2t[c0 * 1152 + idx];
        __syncthreads();

        #pragma unroll
        for (int cc = 0; cc < 8; cc++) {
            float hv[3][6];
            #pragma unroll
            for (int r = 0; r < 3; r++) {
                const float* hp = &hs[cc * 208 + r * 68 + j0];
                float4 h4 = *(const float4*)hp;
                hv[r][0] = h4.x; hv[r][1] = h4.y; hv[r][2] = h4.z; hv[r][3] = h4.w;
                hv[r][4] = hp[4]; hv[r][5] = hp[5];
            }
            #pragma unroll
            for (int kk = 0; kk < 9; kk++) {
                int r = kk / 3, dj = kk % 3;
                const float* wp = &ws[(cc * 9 + kk) * 128 + o0];
                float4 wa = *(const float4*)wp;
                float4 wb = *(const float4*)(wp + 4);
                float wv[8] = {wa.x, wa.y, wa.z, wa.w, wb.x, wb.y, wb.z, wb.w};
                #pragma unroll
                for (int u = 0; u < 8; u++)
                    #pragma unroll
                    for (int v = 0; v < 4; v++)
                        acc[u][v] += wv[u] * hv[r][v + dj];
            }
        }
    }
    #pragma unroll
    for (int u = 0; u < 8; u++) {
        int o = o0 + u;
        float bb = b2[o];
        #pragma unroll
        for (int v = 0; v < 4; v++)
            out[((b * NC + o) * 64 + i) * 64 + j0 + v] = leaky(acc[u][v] + bb);
    }
}

__global__ void k_scoresg(const float* __restrict__ men2rel, const float* __restrict__ score_w,
                          const int* __restrict__ edge_mat, const float* __restrict__ m_bias) {
    int i = blockIdx.x, b = blockIdx.y, j = threadIdx.x;
    __shared__ float sw[128];
    sw[j] = score_w[j]; sw[j + 64] = score_w[j + 64];
    __syncthreads();
    float s = 0.f;
    #pragma unroll 8
    for (int c = 0; c < NC; c++) s += sw[c] * men2rel[((b * NC + c) * 64 + i) * 64 + j];
    int idx = (b * NE + i) * NE + j;
    d_g[idx] = d_L[idx] + leaky(s) + d_eltype[edge_mat[idx]] + m_bias[idx];
}

__global__ __launch_bounds__(256) void k_lin(const float* __restrict__ x, const float* __restrict__ y,
                                             const float* __restrict__ xlw, const float* __restrict__ ylw) {
    __shared__ float wsm[64 * 129];
    int ihalf = blockIdx.x, b = blockIdx.y, z = blockIdx.z;
    const float* w  = z ? ylw : xlw;
    const float* in = z ? y : x;
    float* outp     = z ? d_ylin : d_xlin;
    int t = threadIdx.x;
    int i0b = ihalf * 64;
    for (int idx = t; idx < 64 * 128; idx += 256) {
        int ii = idx >> 7, j = idx & 127;
        wsm[ii * 129 + j] = w[(i0b + ii) * NCIN + j];
    }
    __syncthreads();
    int ig = t >> 4, mg = t & 15;
    int iL0 = ig * 4, m0 = mg * 4;
    float acc[4][4];
    #pragma unroll
    for (int u = 0; u < 4; u++)
        #pragma unroll
        for (int v = 0; v < 4; v++) acc[u][v] = 0.f;
    const float* inb = in + b * NCIN * NE;
    for (int j = 0; j < 128; j++) {
        float av[4], bv[4];
        #pragma unroll
        for (int u = 0; u < 4; u++) av[u] = wsm[(iL0 + u) * 129 + j];
        #pragma unroll
        for (int v = 0; v < 4; v++) bv[v] = inb[j * NE + m0 + v];
        #pragma unroll
        for (int u = 0; u < 4; u++)
            #pragma unroll
            for (int v = 0; v < 4; v++) acc[u][v] += av[u] * bv[v];
    }
    #pragma unroll
    for (int u = 0; u < 4; u++)
        #pragma unroll
        for (int v = 0; v < 4; v++)
            outp[(b * NE + m0 + v) * NCIN + i0b + iL0 + u] = acc[u][v];
}

__global__ __launch_bounds__(256) void k_final(const float* __restrict__ x, const float* __restrict__ y,
                                               float* __restrict__ out) {
    __shared__ float G[64 * 65];
    __shared__ float lin[64 * 65];
    int ihalf = blockIdx.x, b = blockIdx.y, z = blockIdx.z;
    int t = threadIdx.x;
    int i0b = ihalf * 64;
    const float* linsrc = z ? d_xlin : d_ylin;
    for (int idx = t; idx < 4096; idx += 256) {
        int n = idx >> 6, iL = idx & 63;
        lin[n * 65 + iL] = linsrc[(b * NE + n) * NCIN + i0b + iL];
    }
    if (t < 64) {
        int row = t;
        const float* gb = d_g + b * 4096;
        float mx = -1e30f;
        for (int k = 0; k < 64; k++) {
            float gv = z ? gb[k * 64 + row] : gb[row * 64 + k];
            G[row * 65 + k] = gv;
            mx = fmaxf(mx, gv);
        }
        float s = 0.f;
        for (int k = 0; k < 64; k++) { float ev = __expf(G[row * 65 + k] - mx); G[row * 65 + k] = ev; s += ev; }
        float inv = 1.f / s;
        for (int k = 0; k < 64; k++) G[row * 65 + k] *= inv;
    }
    __syncthreads();

    int ig = t >> 4, mg = t & 15;
    int iL0 = ig * 4, m0 = mg * 4;
    float acc[4][4];
    #pragma unroll
    for (int u = 0; u < 4; u++)
        #pragma unroll
        for (int v = 0; v < 4; v++) acc[u][v] = 0.f;
    for (int k = 0; k < 64; k++) {
        float av[4], bv[4];
        #pragma unroll
        for (int u = 0; u < 4; u++) av[u] = lin[k * 65 + iL0 + u];
        #pragma unroll
        for (int v = 0; v < 4; v++) bv[v] = G[(m0 + v) * 65 + k];
        #pragma unroll
        for (int u = 0; u < 4; u++)
            #pragma unroll
            for (int v = 0; v < 4; v++) acc[u][v] += av[u] * bv[v];
    }
    const float* resid = z ? y : x;
    float* outb = out + (z ? NB * NCIN * NE : 0);
    #pragma unroll
    for (int u = 0; u < 4; u++) {
        int i = i0b + iL0 + u;
        #pragma unroll
        for (int v = 0; v < 4; v++) {
            int m = m0 + v;
            outb[(b * NCIN + i) * NE + m] = acc[u][v] + resid[b * NCIN * NE + i * NE + m];
        }
    }
}

extern "C" void kernel_launch(void* const* d_in, const int* in_sizes, int n_in,
                              void* d_out, int out_size) {
    const float* x          = (const float*)d_in[0];
    const float* y          = (const float*)d_in[1];
    const float* m_bias     = (const float*)d_in[2];
    const int*   edge_mat   = (const int*)d_in[3];
    const float* p_bias     = (const float*)d_in[4];
    const int*   path_mat   = (const int*)d_in[5];
    const float* pre_out    = (const float*)d_in[6];
    const float* xc1_w      = (const float*)d_in[7];
    const float* yc1_w      = (const float*)d_in[8];
    const float* xc2_w      = (const float*)d_in[9];
    const float* xc2_b      = (const float*)d_in[10];
    const float* yc2_w      = (const float*)d_in[11];
    const float* yc2_b      = (const float*)d_in[12];
    const float* pconv_w    = (const float*)d_in[13];
    const float* econv_w    = (const float*)d_in[14];
    const float* conv1_w    = (const float*)d_in[15];
    const float* conv1_b    = (const float*)d_in[16];
    const float* conv2_w    = (const float*)d_in[17];
    const float* conv2_b    = (const float*)d_in[18];
    const float* score_w    = (const float*)d_in[19];
    const float* xlin_w     = (const float*)d_in[20];
    const float* ylin_w     = (const float*)d_in[21];
    const float* edge_table = (const float*)d_in[22];
    const float* path_table = (const float*)d_in[23];

    float* out = (float*)d_out;
    float* out_men2rel = out + 2 * NB * NCIN * NE;

    k_prep<<<1, 32>>>(path_table, pconv_w, edge_table, econv_w);
    k_w2t<<<(NC * NC * 9 + 255) / 256, 256>>>(conv2_w);
    { dim3 g(NC, NB, 2); k_xfyf<<<g, 64>>>(x, y, xc1_w, yc1_w); }
    k_selflog<<<NB, 128>>>(xc2_w, xc2_b, yc2_w, yc2_b);
    { dim3 g(NE, NB); k_attn<<<g, 256>>>(path_mat, p_bias); }
    { dim3 g(32, NB); k_conv1<<<g, 256>>>(pre_out, conv1_w, conv1_b); }
    { dim3 g(64, NB); k_conv2<<<g, 256>>>(conv2_b, out_men2rel); }
    { dim3 g(64, NB); k_scoresg<<<g, 64>>>(out_men2rel, score_w, edge_mat, m_bias); }
    { dim3 g(2, NB, 2); k_lin<<<g, 256>>>(x, y, xlin_w, ylin_w); }
    { dim3 g(2, NB, 2); k_final<<<g, 256>>>(x, y, out); }
}

// round 5
// speedup vs baseline: 1.9797x; 1.9797x over previous
#include <cuda_runtime.h>
#include <cuda_fp16.h>
#include <cstdint>

constexpr int NB = 8, NE = 64, NCIN = 128, NC = 128;

__device__ __forceinline__ float leaky(float v) { return v >= 0.f ? v : 0.1f * v; }

// ---------------- scratch (static device globals) ----------------
__device__ float  d_xf[NB * NC * NE];
__device__ float  d_yf[NB * NC * NE];
__device__ float  d_L[NB * NE * NE];
__device__ float  d_pltype[20];
__device__ float  d_eltype[10];
__device__ float  d_wx[NCIN];
__device__ float  d_wy[NCIN];
__device__ float  d_g[NB * NE * NE];
__device__ float  d_xlin[NB * NE * NCIN];
__device__ float  d_ylin[NB * NE * NCIN];
__device__ __half d_menh[NB * 384 * 4096];   // conv1 input  [b][k=384][p=4096]
__device__ __half d_hh[NB * NC * 4096];      // conv1 output [b][c][p]
__device__ __half d_w1h[NC * 384];           // conv1 weights half
__device__ __half d_w2s[9 * NC * NC];        // conv2 weights [shift][o][c] half

__device__ __forceinline__ uint32_t smem_to_u32(const void* p) {
    uint32_t a;
    asm("{ .reg .u64 t; cvta.to.shared.u64 t, %1; cvt.u32.u64 %0, t; }" : "=r"(a) : "l"(p));
    return a;
}
#define LDSM_X4(r0, r1, r2, r3, addr) \
    asm volatile("ldmatrix.sync.aligned.m8n8.x4.shared.b16 {%0,%1,%2,%3}, [%4];" \
        : "=r"(r0), "=r"(r1), "=r"(r2), "=r"(r3) : "r"(addr))
#define LDSM_X2(r0, r1, addr) \
    asm volatile("ldmatrix.sync.aligned.m8n8.x2.shared.b16 {%0,%1}, [%2];" \
        : "=r"(r0), "=r"(r1) : "r"(addr))
__device__ __forceinline__ void mma16816(float* c, const uint32_t* a, const uint32_t* b) {
    asm volatile("mma.sync.aligned.m16n8k16.row.col.f32.f16.f16.f32 "
                 "{%0,%1,%2,%3}, {%4,%5,%6,%7}, {%8,%9}, {%0,%1,%2,%3};"
                 : "+f"(c[0]), "+f"(c[1]), "+f"(c[2]), "+f"(c[3])
                 : "r"(a[0]), "r"(a[1]), "r"(a[2]), "r"(a[3]), "r"(b[0]), "r"(b[1]));
}
constexpr int PITCH = 72;   // halfs; 144B rows, 16B-aligned, ldmatrix conflict-free

// ---------------- prep ----------------
__global__ void k_prep(const float* __restrict__ path_table, const float* __restrict__ pconv_w,
                       const float* __restrict__ edge_table, const float* __restrict__ econv_w,
                       const float* __restrict__ xc1_w, const float* __restrict__ yc1_w,
                       const float* __restrict__ xc2_w, const float* __restrict__ yc2_w) {
    int t = threadIdx.x;
    if (t < 20) {
        float s = 0.f;
        #pragma unroll
        for (int d = 0; d < 32; d++) s += path_table[t * 32 + d] * pconv_w[d];
        d_pltype[t] = leaky(s);
    }
    if (t < 10) {
        float s = 0.f;
        #pragma unroll
        for (int d = 0; d < 32; d++) s += edge_table[t * 32 + d] * econv_w[d];
        d_eltype[t] = leaky(s);
    }
    float ax = 0.f, ay = 0.f;
    #pragma unroll 8
    for (int c = 0; c < NC; c++) {
        ax += xc2_w[c] * xc1_w[c * NCIN + t];
        ay += yc2_w[c] * yc1_w[c * NCIN + t];
    }
    d_wx[t] = ax; d_wy[t] = ay;
}

__global__ void k_w1h(const float* __restrict__ w1) {
    int i = blockIdx.x * 256 + threadIdx.x;
    if (i < NC * 384) d_w1h[i] = __float2half(w1[i]);
}

__global__ void k_w2s(const float* __restrict__ w2) {
    int i = blockIdx.x * 256 + threadIdx.x;
    if (i < 9 * NC * NC) {
        int shift = i / 16384, rem = i % 16384;
        int o = rem >> 7, c = rem & 127;
        d_w2s[i] = __float2half(w2[(o * NC + c) * 9 + shift]);
    }
}

__global__ void k_pre2h(const float* __restrict__ pre) {
    int i = blockIdx.x * 256 + threadIdx.x;
    int p2 = i * 2;
    int b = p2 >> 19, rem = p2 & 524287;
    int c = rem >> 12, p = rem & 4095;
    float2 f = ((const float2*)pre)[i];
    ((__half2*)d_menh)[(b * 384 + 256 + c) * 2048 + (p >> 1)] = __floats2half2_rn(f.x, f.y);
}

// ---------------- x_f / y_f ----------------
__global__ void k_xfyf(const float* __restrict__ x, const float* __restrict__ y,
                       const float* __restrict__ xw, const float* __restrict__ yw) {
    int c = blockIdx.x, b = blockIdx.y;
    const float* in = blockIdx.z ? y : x;
    const float* w  = blockIdx.z ? yw : xw;
    float* out      = blockIdx.z ? d_yf : d_xf;
    __shared__ float ws[NCIN];
    int m = threadIdx.x;
    for (int i = m; i < NCIN; i += 64) ws[i] = w[c * NCIN + i];
    __syncthreads();
    const float* inb = in + b * NCIN * NE + m;
    float acc = 0.f;
    #pragma unroll 8
    for (int i = 0; i < NCIN; i++) acc += ws[i] * inb[i * NE];
    out[(b * NC + c) * NE + m] = acc;
}

// ---------------- x_self / y_other / L ----------------
__global__ void k_selfL(const float* __restrict__ x, const float* __restrict__ y,
                        const float* __restrict__ xc2_b, const float* __restrict__ yc2_b) {
    int b = blockIdx.x, t = threadIdx.x;
    __shared__ float xs[NE], yo[NE];
    if (t < 64) {
        const float* xb = x + b * NCIN * NE + t;
        float a0 = 0.f, a1 = 0.f;
        #pragma unroll 8
        for (int i = 0; i < NCIN; i += 2) { a0 += d_wx[i] * xb[i * NE]; a1 += d_wx[i + 1] * xb[(i + 1) * NE]; }
        xs[t] = a0 + a1 + xc2_b[0];
    } else {
        int m = t - 64;
        const float* yb = y + b * NCIN * NE + m;
        float a0 = 0.f, a1 = 0.f;
        #pragma unroll 8
        for (int i = 0; i < NCIN; i += 2) { a0 += d_wy[i] * yb[i * NE]; a1 += d_wy[i + 1] * yb[(i + 1) * NE]; }
        yo[m] = a0 + a1 + yc2_b[0];
    }
    __syncthreads();
    for (int idx = t; idx < NE * NE; idx += 128) {
        int p = idx >> 6, q = idx & 63;
        d_L[b * NE * NE + idx] = leaky(xs[q] + yo[p]);
    }
}

// ---------------- per-(b,e) path attention ----------------
__global__ __launch_bounds__(256) void k_attn(const int* __restrict__ path_mat,
                                              const float* __restrict__ p_bias) {
    __shared__ float loc[64 * 65];
    __shared__ float Asm[64 * 65];
    __shared__ float cmax[64], cinv[64];
    int e = blockIdx.x, b = blockIdx.y, t = threadIdx.x;
    const int*   pm = path_mat + (b * NE + e) * 4096;
    const float* pb = p_bias  + (size_t)(b * NE + e) * 4096;
    const float* Lb = d_L + b * 4096;

    for (int idx = t; idx < 4096; idx += 256) {
        int m = idx >> 6, n = idx & 63;
        loc[m * 65 + n] = Lb[idx] + d_pltype[pm[idx]] + pb[idx];
    }
    __syncthreads();

    if (t < 64) {
        float mx = -1e30f;
        for (int n = 0; n < 64; n++) mx = fmaxf(mx, loc[t * 65 + n]);
        float s = 0.f;
        for (int n = 0; n < 64; n++) { float ev = __expf(loc[t * 65 + n] - mx); Asm[t * 65 + n] = ev; s += ev; }
        float inv = 1.f / s;
        for (int n = 0; n < 64; n++) Asm[t * 65 + n] *= inv;
    } else if (t < 128) {
        int n = t - 64;
        float mx = -1e30f;
        for (int m = 0; m < 64; m++) mx = fmaxf(mx, loc[m * 65 + n]);
        float s = 0.f;
        for (int m = 0; m < 64; m++) s += __expf(loc[m * 65 + n] - mx);
        cmax[n] = mx; cinv[n] = 1.f / s;
    }
    __syncthreads();

    for (int idx = t; idx < 4096; idx += 256) {
        int m = idx >> 6, n = idx & 63;
        loc[m * 65 + n] = __expf(loc[m * 65 + n] - cmax[n]) * cinv[n];
    }
    __syncthreads();

    int c0 = (t >> 4) * 8;
    int m0 = (t & 15) * 4;
    float accx[8][4], accy[8][4];
    #pragma unroll
    for (int u = 0; u < 8; u++)
        #pragma unroll
        for (int v = 0; v < 4; v++) { accx[u][v] = 0.f; accy[u][v] = 0.f; }
    const float* yfb = d_yf + b * NC * NE;
    const float* xfb = d_xf + b * NC * NE;
    for (int k = 0; k < 64; k++) {
        float ax[8], ay[8], bx[4], by[4];
        #pragma unroll
        for (int u = 0; u < 8; u++) {
            ax[u] = yfb[(c0 + u) * NE + k];
            ay[u] = xfb[(c0 + u) * NE + k];
        }
        #pragma unroll
        for (int v = 0; v < 4; v++) {
            bx[v] = Asm[(m0 + v) * 65 + k];
            by[v] = loc[k * 65 + m0 + v];
        }
        #pragma unroll
        for (int u = 0; u < 8; u++)
            #pragma unroll
            for (int v = 0; v < 4; v++) {
                accx[u][v] += ax[u] * bx[v];
                accy[u][v] += ay[u] * by[v];
            }
    }
    #pragma unroll
    for (int u = 0; u < 8; u++) {
        int c = c0 + u;
        #pragma unroll
        for (int v = 0; v < 4; v += 2) {
            int m = m0 + v;
            float vx0 = leaky(accx[u][v]     + xfb[c * NE + m]);
            float vx1 = leaky(accx[u][v + 1] + xfb[c * NE + m + 1]);
            float vy0 = leaky(accy[u][v]     + yfb[c * NE + m]);
            float vy1 = leaky(accy[u][v + 1] + yfb[c * NE + m + 1]);
            *(__half2*)&d_menh[(size_t)(b * 384 + c) * 4096 + e * 64 + m]       = __floats2half2_rn(vx0, vx1);
            *(__half2*)&d_menh[(size_t)(b * 384 + 128 + c) * 4096 + e * 64 + m] = __floats2half2_rn(vy0, vy1);
        }
    }
}

// ---------------- conv1 via mma.sync: [128,384]@[384,128tile] ----------------
__global__ __launch_bounds__(256) void k_conv1_mma(const float* __restrict__ b1) {
    __shared__ __align__(16) __half As[128 * PITCH];
    __shared__ __align__(16) __half Bs[128 * PITCH];
    int tid = threadIdx.x, lane = tid & 31, w = tid >> 5;
    int wm = w >> 2, wn = w & 3;
    int tile = blockIdx.x, b = blockIdx.y;
    int p0 = tile * 128;
    uint32_t smA = smem_to_u32(As), smB = smem_to_u32(Bs);
    const uint32_t* w32 = (const uint32_t*)d_w1h;
    float acc[4][4][4];
    #pragma unroll
    for (int mi = 0; mi < 4; mi++)
        #pragma unroll
        for (int ni = 0; ni < 4; ni++)
            #pragma unroll
            for (int q = 0; q < 4; q++) acc[mi][ni][q] = 0.f;

    for (int k0 = 0; k0 < 384; k0 += 64) {
        __syncthreads();
        for (int idx = tid; idx < 4096; idx += 256) {         // A [o][k]
            int row = idx >> 5, cp = idx & 31;
            *(uint32_t*)&As[row * PITCH + cp * 2] = w32[row * 192 + (k0 >> 1) + cp];
        }
        for (int idx = tid; idx < 4096; idx += 256) {         // B transpose -> [p][k]
            int kk = idx >> 6, pp = (idx & 63) * 2;
            uint32_t v = *(const uint32_t*)(d_menh + (size_t)(b * 384 + k0 + kk) * 4096 + p0 + pp);
            ((unsigned short*)Bs)[pp * PITCH + kk]       = (unsigned short)v;
            ((unsigned short*)Bs)[(pp + 1) * PITCH + kk] = (unsigned short)(v >> 16);
        }
        __syncthreads();
        #pragma unroll
        for (int ks = 0; ks < 4; ks++) {
            uint32_t a[4][4], bf[4][2];
            #pragma unroll
            for (int mi = 0; mi < 4; mi++) {
                uint32_t ad = smA + ((wm * 64 + mi * 16 + (lane & 15)) * PITCH + ks * 16 + (lane >> 4) * 8) * 2;
                LDSM_X4(a[mi][0], a[mi][1], a[mi][2], a[mi][3], ad);
            }
            #pragma unroll
            for (int ni = 0; ni < 4; ni++) {
                uint32_t ad = smB + ((wn * 32 + ni * 8 + (lane & 7)) * PITCH + ks * 16 + ((lane >> 3) & 1) * 8) * 2;
                LDSM_X2(bf[ni][0], bf[ni][1], ad);
            }
            #pragma unroll
            for (int mi = 0; mi < 4; mi++)
                #pragma unroll
                for (int ni = 0; ni < 4; ni++) mma16816(acc[mi][ni], a[mi], bf[ni]);
        }
    }

    int mrow = lane >> 2, ncol = (lane & 3) * 2;
    #pragma unroll
    for (int mi = 0; mi < 4; mi++) {
        int o = wm * 64 + mi * 16 + mrow;
        float bb0 = b1[o], bb1 = b1[o + 8];
        #pragma unroll
        for (int ni = 0; ni < 4; ni++) {
            int p = p0 + wn * 32 + ni * 8 + ncol;
            __half* dst = d_hh + (size_t)(b * NC + o) * 4096 + p;
            *(__half2*)dst = __floats2half2_rn(leaky(acc[mi][ni][0] + bb0), leaky(acc[mi][ni][1] + bb0));
            *(__half2*)(dst + (size_t)8 * 4096) = __floats2half2_rn(leaky(acc[mi][ni][2] + bb1), leaky(acc[mi][ni][3] + bb1));
        }
    }
}

// ---------------- conv2 3x3 via mma.sync: 9 shifted GEMMs, K=1152 ----------------
__global__ __launch_bounds__(256) void k_conv2_mma(const float* __restrict__ b2,
                                                   float* __restrict__ out) {
    __shared__ __align__(16) __half As[128 * PITCH];
    __shared__ __align__(16) __half Bs[128 * PITCH];
    int tid = threadIdx.x, lane = tid & 31, w = tid >> 5;
    int wm = w >> 2, wn = w & 3;
    int tile = blockIdx.x, b = blockIdx.y;
    int p0 = tile * 128;
    uint32_t smA = smem_to_u32(As), smB = smem_to_u32(Bs);
    const uint32_t* w32 = (const uint32_t*)d_w2s;
    const unsigned short* hh = (const unsigned short*)d_hh;
    float acc[4][4][4];
    #pragma unroll
    for (int mi = 0; mi < 4; mi++)
        #pragma unroll
        for (int ni = 0; ni < 4; ni++)
            #pragma unroll
            for (int q = 0; q < 4; q++) acc[mi][ni][q] = 0.f;

    for (int it = 0; it < 18; it++) {
        int shift = it >> 1;
        int c0 = (it & 1) * 64;
        int r = shift / 3 - 1, s = shift % 3 - 1;
        __syncthreads();
        for (int idx = tid; idx < 4096; idx += 256) {          // A: w2s[shift][o][c0..+63]
            int row = idx >> 5, cp = idx & 31;
            *(uint32_t*)&As[row * PITCH + cp * 2] = w32[shift * 8192 + row * 64 + (c0 >> 1) + cp];
        }
        for (int idx = tid; idx < 8192; idx += 256) {          // B: shifted h gather -> [p][c]
            int cc = idx >> 7, p = idx & 127;
            int pix = p0 + p;
            int ii = (pix >> 6) + r;
            int jj = (pix & 63) + s;
            unsigned short v = 0;
            if ((unsigned)ii < 64u && (unsigned)jj < 64u)
                v = hh[((size_t)(b * NC + c0 + cc) << 12) + ii * 64 + jj];
            ((unsigned short*)Bs)[p * PITCH + cc] = v;
        }
        __syncthreads();
        #pragma unroll
        for (int ks = 0; ks < 4; ks++) {
            uint32_t a[4][4], bf[4][2];
            #pragma unroll
            for (int mi = 0; mi < 4; mi++) {
                uint32_t ad = smA + ((wm * 64 + mi * 16 + (lane & 15)) * PITCH + ks * 16 + (lane >> 4) * 8) * 2;
                LDSM_X4(a[mi][0], a[mi][1], a[mi][2], a[mi][3], ad);
            }
            #pragma unroll
            for (int ni = 0; ni < 4; ni++) {
                uint32_t ad = smB + ((wn * 32 + ni * 8 + (lane & 7)) * PITCH + ks * 16 + ((lane >> 3) & 1) * 8) * 2;
                LDSM_X2(bf[ni][0], bf[ni][1], ad);
            }
            #pragma unroll
            for (int mi = 0; mi < 4; mi++)
                #pragma unroll
                for (int ni = 0; ni < 4; ni++) mma16816(acc[mi][ni], a[mi], bf[ni]);
        }
    }

    int mrow = lane >> 2, ncol = (lane & 3) * 2;
    #pragma unroll
    for (int mi = 0; mi < 4; mi++) {
        int o = wm * 64 + mi * 16 + mrow;
        float bb0 = b2[o], bb1 = b2[o + 8];
        #pragma unroll
        for (int ni = 0; ni < 4; ni++) {
            int p = p0 + wn * 32 + ni * 8 + ncol;
            float* dst = out + (size_t)(b * NC + o) * 4096 + p;
            float2 v0 = make_float2(leaky(acc[mi][ni][0] + bb0), leaky(acc[mi][ni][1] + bb0));
            float2 v1 = make_float2(leaky(acc[mi][ni][2] + bb1), leaky(acc[mi][ni][3] + bb1));
            *(float2*)dst = v0;
            *(float2*)(dst + (size_t)8 * 4096) = v1;
        }
    }
}

// ---------------- scores + g ----------------
__global__ void k_scoresg(const float* __restrict__ men2rel, const float* __restrict__ score_w,
                          const int* __restrict__ edge_mat, const float* __restrict__ m_bias) {
    int i = blockIdx.x, b = blockIdx.y, j = threadIdx.x;
    __shared__ float sw[128];
    sw[j] = score_w[j]; sw[j + 64] = score_w[j + 64];
    __syncthreads();
    float s = 0.f;
    #pragma unroll 8
    for (int c = 0; c < NC; c++) s += sw[c] * men2rel[((b * NC + c) * 64 + i) * 64 + j];
    int idx = (b * NE + i) * NE + j;
    d_g[idx] = d_L[idx] + leaky(s) + d_eltype[edge_mat[idx]] + m_bias[idx];
}

// ---------------- x_lin / y_lin ----------------
__global__ __launch_bounds__(256) void k_lin(const float* __restrict__ x, const float* __restrict__ y,
                                             const float* __restrict__ xlw, const float* __restrict__ ylw) {
    __shared__ float wsm[64 * 129];
    int ihalf = blockIdx.x, b = blockIdx.y, z = blockIdx.z;
    const float* w  = z ? ylw : xlw;
    const float* in = z ? y : x;
    float* outp     = z ? d_ylin : d_xlin;
    int t = threadIdx.x;
    int i0b = ihalf * 64;
    for (int idx = t; idx < 64 * 128; idx += 256) {
        int ii = idx >> 7, j = idx & 127;
        wsm[ii * 129 + j] = w[(i0b + ii) * NCIN + j];
    }
    __syncthreads();
    int ig = t >> 4, mg = t & 15;
    int iL0 = ig * 4, m0 = mg * 4;
    float acc[4][4];
    #pragma unroll
    for (int u = 0; u < 4; u++)
        #pragma unroll
        for (int v = 0; v < 4; v++) acc[u][v] = 0.f;
    const float* inb = in + b * NCIN * NE;
    for (int j = 0; j < 128; j++) {
        float av[4], bv[4];
        #pragma unroll
        for (int u = 0; u < 4; u++) av[u] = wsm[(iL0 + u) * 129 + j];
        #pragma unroll
        for (int v = 0; v < 4; v++) bv[v] = inb[j * NE + m0 + v];
        #pragma unroll
        for (int u = 0; u < 4; u++)
            #pragma unroll
            for (int v = 0; v < 4; v++) acc[u][v] += av[u] * bv[v];
    }
    #pragma unroll
    for (int u = 0; u < 4; u++)
        #pragma unroll
        for (int v = 0; v < 4; v++)
            outp[(b * NE + m0 + v) * NCIN + i0b + iL0 + u] = acc[u][v];
}

// ---------------- final softmax + output GEMMs ----------------
__global__ __launch_bounds__(256) void k_final(const float* __restrict__ x, const float* __restrict__ y,
                                               float* __restrict__ out) {
    __shared__ float G[64 * 65];
    __shared__ float lin[64 * 65];
    int ihalf = blockIdx.x, b = blockIdx.y, z = blockIdx.z;
    int t = threadIdx.x;
    int i0b = ihalf * 64;
    const float* linsrc = z ? d_xlin : d_ylin;
    for (int idx = t; idx < 4096; idx += 256) {
        int n = idx >> 6, iL = idx & 63;
        lin[n * 65 + iL] = linsrc[(b * NE + n) * NCIN + i0b + iL];
    }
    if (t < 64) {
        int row = t;
        const float* gb = d_g + b * 4096;
        float mx = -1e30f;
        for (int k = 0; k < 64; k++) {
            float gv = z ? gb[k * 64 + row] : gb[row * 64 + k];
            G[row * 65 + k] = gv;
            mx = fmaxf(mx, gv);
        }
        float s = 0.f;
        for (int k = 0; k < 64; k++) { float ev = __expf(G[row * 65 + k] - mx); G[row * 65 + k] = ev; s += ev; }
        float inv = 1.f / s;
        for (int k = 0; k < 64; k++) G[row * 65 + k] *= inv;
    }
    __syncthreads();

    int ig = t >> 4, mg = t & 15;
    int iL0 = ig * 4, m0 = mg * 4;
    float acc[4][4];
    #pragma unroll
    for (int u = 0; u < 4; u++)
        #pragma unroll
        for (int v = 0; v < 4; v++) acc[u][v] = 0.f;
    for (int k = 0; k < 64; k++) {
        float av[4], bv[4];
        #pragma unroll
        for (int u = 0; u < 4; u++) av[u] = lin[k * 65 + iL0 + u];
        #pragma unroll
        for (int v = 0; v < 4; v++) bv[v] = G[(m0 + v) * 65 + k];
        #pragma unroll
        for (int u = 0; u < 4; u++)
            #pragma unroll
            for (int v = 0; v < 4; v++) acc[u][v] += av[u] * bv[v];
    }
    const float* resid = z ? y : x;
    float* outb = out + (z ? NB * NCIN * NE : 0);
    #pragma unroll
    for (int u = 0; u < 4; u++) {
        int i = i0b + iL0 + u;
        #pragma unroll
        for (int v = 0; v < 4; v++) {
            int m = m0 + v;
            outb[(b * NCIN + i) * NE + m] = acc[u][v] + resid[b * NCIN * NE + i * NE + m];
        }
    }
}

extern "C" void kernel_launch(void* const* d_in, const int* in_sizes, int n_in,
                              void* d_out, int out_size) {
    const float* x          = (const float*)d_in[0];
    const float* y          = (const float*)d_in[1];
    const float* m_bias     = (const float*)d_in[2];
    const int*   edge_mat   = (const int*)d_in[3];
    const float* p_bias     = (const float*)d_in[4];
    const int*   path_mat   = (const int*)d_in[5];
    const float* pre_out    = (const float*)d_in[6];
    const float* xc1_w      = (const float*)d_in[7];
    const float* yc1_w      = (const float*)d_in[8];
    const float* xc2_w      = (const float*)d_in[9];
    const float* xc2_b      = (const float*)d_in[10];
    const float* yc2_w      = (const float*)d_in[11];
    const float* yc2_b      = (const float*)d_in[12];
    const float* pconv_w    = (const float*)d_in[13];
    const float* econv_w    = (const float*)d_in[14];
    const float* conv1_w    = (const float*)d_in[15];
    const float* conv1_b    = (const float*)d_in[16];
    const float* conv2_w    = (const float*)d_in[17];
    const float* conv2_b    = (const float*)d_in[18];
    const float* score_w    = (const float*)d_in[19];
    const float* xlin_w     = (const float*)d_in[20];
    const float* ylin_w     = (const float*)d_in[21];
    const float* edge_table = (const float*)d_in[22];
    const float* path_table = (const float*)d_in[23];

    float* out = (float*)d_out;
    float* out_men2rel = out + 2 * NB * NCIN * NE;

    k_prep<<<1, 128>>>(path_table, pconv_w, edge_table, econv_w, xc1_w, yc1_w, xc2_w, yc2_w);
    k_w1h<<<192, 256>>>(conv1_w);
    k_w2s<<<576, 256>>>(conv2_w);
    k_pre2h<<<8192, 256>>>(pre_out);
    { dim3 g(NC, NB, 2); k_xfyf<<<g, 64>>>(x, y, xc1_w, yc1_w); }
    k_selfL<<<NB, 128>>>(x, y, xc2_b, yc2_b);
    { dim3 g(NE, NB); k_attn<<<g, 256>>>(path_mat, p_bias); }
    { dim3 g(32, NB); k_conv1_mma<<<g, 256>>>(conv1_b); }
    { dim3 g(32, NB); k_conv2_mma<<<g, 256>>>(conv2_b, out_men2rel); }
    { dim3 g(64, NB); k_scoresg<<<g, 64>>>(out_men2rel, score_w, edge_mat, m_bias); }
    { dim3 g(2, NB, 2); k_lin<<<g, 256>>>(x, y, xlin_w, ylin_w); }
    { dim3 g(2, NB, 2); k_final<<<g, 256>>>(x, y, out); }
}

// round 6
// speedup vs baseline: 2.3300x; 1.1769x over previous
#include <cuda_runtime.h>
#include <cuda_fp16.h>
#include <cstdint>

constexpr int NB = 8, NE = 64, NCIN = 128, NC = 128;

__device__ __forceinline__ float leaky(float v) { return v >= 0.f ? v : 0.1f * v; }

// ---------------- scratch (static device globals) ----------------
__device__ float  d_xf[NB * NC * NE];
__device__ float  d_yf[NB * NC * NE];
__device__ float  d_L[NB * NE * NE];
__device__ float  d_pltype[20];
__device__ float  d_eltype[10];
__device__ float  d_wx[NCIN];
__device__ float  d_wy[NCIN];
__device__ float  d_g[NB * NE * NE];
__device__ float  d_xlin[NB * NE * NCIN];
__device__ float  d_ylin[NB * NE * NCIN];
__device__ __half d_menh[NB * 256 * 4096];   // conv1 input rows 0..255 (path_fea) [b][c][p]
__device__ __half d_hh[NB * NC * 4096];      // conv1 output [b][c][p]
__device__ __half d_w1h[NC * 384];           // conv1 weights half
__device__ __half d_w2s[9 * NC * NC];        // conv2 weights [shift][o][c] half

__device__ __forceinline__ uint32_t smem_to_u32(const void* p) {
    uint32_t a;
    asm("{ .reg .u64 t; cvta.to.shared.u64 t, %1; cvt.u32.u64 %0, t; }" : "=r"(a) : "l"(p));
    return a;
}
#define LDSM_X4(r0, r1, r2, r3, addr) \
    asm volatile("ldmatrix.sync.aligned.m8n8.x4.shared.b16 {%0,%1,%2,%3}, [%4];" \
        : "=r"(r0), "=r"(r1), "=r"(r2), "=r"(r3) : "r"(addr))
#define LDSM_X2(r0, r1, addr) \
    asm volatile("ldmatrix.sync.aligned.m8n8.x2.shared.b16 {%0,%1}, [%2];" \
        : "=r"(r0), "=r"(r1) : "r"(addr))
__device__ __forceinline__ void mma16816(float* c, const uint32_t* a, const uint32_t* b) {
    asm volatile("mma.sync.aligned.m16n8k16.row.col.f32.f16.f16.f32 "
                 "{%0,%1,%2,%3}, {%4,%5,%6,%7}, {%8,%9}, {%0,%1,%2,%3};"
                 : "+f"(c[0]), "+f"(c[1]), "+f"(c[2]), "+f"(c[3])
                 : "r"(a[0]), "r"(a[1]), "r"(a[2]), "r"(a[3]), "r"(b[0]), "r"(b[1]));
}
constexpr int PITCH = 72;   // halfs; 144B rows, 16B-aligned, ldmatrix conflict-free

// ---------------- prep ----------------
__global__ void k_prep(const float* __restrict__ path_table, const float* __restrict__ pconv_w,
                       const float* __restrict__ edge_table, const float* __restrict__ econv_w,
                       const float* __restrict__ xc1_w, const float* __restrict__ yc1_w,
                       const float* __restrict__ xc2_w, const float* __restrict__ yc2_w) {
    int t = threadIdx.x;
    if (t < 20) {
        float s = 0.f;
        #pragma unroll
        for (int d = 0; d < 32; d++) s += path_table[t * 32 + d] * pconv_w[d];
        d_pltype[t] = leaky(s);
    }
    if (t < 10) {
        float s = 0.f;
        #pragma unroll
        for (int d = 0; d < 32; d++) s += edge_table[t * 32 + d] * econv_w[d];
        d_eltype[t] = leaky(s);
    }
    float ax = 0.f, ay = 0.f;
    #pragma unroll 8
    for (int c = 0; c < NC; c++) {
        ax += xc2_w[c] * xc1_w[c * NCIN + t];
        ay += yc2_w[c] * yc1_w[c * NCIN + t];
    }
    d_wx[t] = ax; d_wy[t] = ay;
}

__global__ void k_w1h(const float* __restrict__ w1) {
    int i = blockIdx.x * 256 + threadIdx.x;
    if (i < NC * 384) d_w1h[i] = __float2half(w1[i]);
}

__global__ void k_w2s(const float* __restrict__ w2) {
    int i = blockIdx.x * 256 + threadIdx.x;
    if (i < 9 * NC * NC) {
        int shift = i / 16384, rem = i % 16384;
        int o = rem >> 7, c = rem & 127;
        d_w2s[i] = __float2half(w2[(o * NC + c) * 9 + shift]);
    }
}

// ---------------- x_f / y_f ----------------
__global__ void k_xfyf(const float* __restrict__ x, const float* __restrict__ y,
                       const float* __restrict__ xw, const float* __restrict__ yw) {
    int c = blockIdx.x, b = blockIdx.y;
    const float* in = blockIdx.z ? y : x;
    const float* w  = blockIdx.z ? yw : xw;
    float* out      = blockIdx.z ? d_yf : d_xf;
    __shared__ float ws[NCIN];
    int m = threadIdx.x;
    for (int i = m; i < NCIN; i += 64) ws[i] = w[c * NCIN + i];
    __syncthreads();
    const float* inb = in + b * NCIN * NE + m;
    float acc = 0.f;
    #pragma unroll 8
    for (int i = 0; i < NCIN; i++) acc += ws[i] * inb[i * NE];
    out[(b * NC + c) * NE + m] = acc;
}

// ---------------- x_self / y_other / L ----------------
__global__ void k_selfL(const float* __restrict__ x, const float* __restrict__ y,
                        const float* __restrict__ xc2_b, const float* __restrict__ yc2_b) {
    int b = blockIdx.x, t = threadIdx.x;
    __shared__ float xs[NE], yo[NE];
    if (t < 64) {
        const float* xb = x + b * NCIN * NE + t;
        float a0 = 0.f, a1 = 0.f;
        #pragma unroll 8
        for (int i = 0; i < NCIN; i += 2) { a0 += d_wx[i] * xb[i * NE]; a1 += d_wx[i + 1] * xb[(i + 1) * NE]; }
        xs[t] = a0 + a1 + xc2_b[0];
    } else {
        int m = t - 64;
        const float* yb = y + b * NCIN * NE + m;
        float a0 = 0.f, a1 = 0.f;
        #pragma unroll 8
        for (int i = 0; i < NCIN; i += 2) { a0 += d_wy[i] * yb[i * NE]; a1 += d_wy[i + 1] * yb[(i + 1) * NE]; }
        yo[m] = a0 + a1 + yc2_b[0];
    }
    __syncthreads();
    for (int idx = t; idx < NE * NE; idx += 128) {
        int p = idx >> 6, q = idx & 63;
        d_L[b * NE * NE + idx] = leaky(xs[q] + yo[p]);
    }
}

// ---------------- per-(b,e) path attention: softmax fp32 + mma.sync GEMMs ----------------
__global__ __launch_bounds__(256) void k_attn(const int* __restrict__ path_mat,
                                              const float* __restrict__ p_bias) {
    __shared__ __align__(16) float  loc[64 * 64];     // logits, pitch 64
    __shared__ __align__(16) __half Ah[64 * 64];      // softmax half (swizzled rows of 128B)
    __shared__ __align__(16) __half Fh[128 * 64];     // yf then xf halves (swizzled)
    __shared__ float rmax[64], rinv[64], cmax[64], cinv[64];
    int e = blockIdx.x, b = blockIdx.y, t = threadIdx.x;
    int lane = t & 31, w = t >> 5;
    const int*   pm = path_mat + (b * NE + e) * 4096;
    const float* pb = p_bias  + (size_t)(b * NE + e) * 4096;
    const float* Lb = d_L + b * 4096;
    const float* xfb = d_xf + b * NC * NE;
    const float* yfb = d_yf + b * NC * NE;
    uint32_t AhB = smem_to_u32(Ah), FhB = smem_to_u32(Fh);

    // phase 0: logits + stage yf as half (swizzled [c][n])
    for (int idx = t; idx < 4096; idx += 256)
        loc[idx] = Lb[idx] + d_pltype[pm[idx]] + pb[idx];
    for (int idx = t; idx < 4096; idx += 256) {
        int c = idx >> 5, n2 = idx & 31;
        float2 f = *(const float2*)(yfb + c * 64 + n2 * 2);
        uint32_t off = c * 128 + ((n2 * 4) ^ ((c & 7) * 16));
        *(__half2*)((char*)Fh + off) = __floats2half2_rn(f.x, f.y);
    }
    __syncthreads();

    // phase 1: row stats (warp w -> rows w*8..w*8+7), lane-parallel
    {
        int row = w * 8;
        #pragma unroll
        for (int rr = 0; rr < 8; rr++) {
            float v0 = loc[(row + rr) * 64 + lane];
            float v1 = loc[(row + rr) * 64 + 32 + lane];
            float mx = fmaxf(v0, v1);
            #pragma unroll
            for (int o = 16; o > 0; o >>= 1) mx = fmaxf(mx, __shfl_xor_sync(0xffffffff, mx, o));
            float s = __expf(v0 - mx) + __expf(v1 - mx);
            #pragma unroll
            for (int o = 16; o > 0; o >>= 1) s += __shfl_xor_sync(0xffffffff, s, o);
            if (lane == 0) { rmax[row + rr] = mx; rinv[row + rr] = 1.f / s; }
        }
    }
    // col stats: threads 0..63 walk rows (coalesced)
    if (t < 64) {
        float mx = -1e30f;
        for (int m = 0; m < 64; m++) mx = fmaxf(mx, loc[m * 64 + t]);
        float s = 0.f;
        for (int m = 0; m < 64; m++) s += __expf(loc[m * 64 + t] - mx);
        cmax[t] = mx; cinv[t] = 1.f / s;
    }
    __syncthreads();

    // phase 2: Ah[m][n] = row softmax (half, swizzled)
    for (int idx = t; idx < 2048; idx += 256) {
        int m = idx >> 5, n2 = idx & 31;
        float v0 = __expf(loc[m * 64 + n2 * 2]     - rmax[m]) * rinv[m];
        float v1 = __expf(loc[m * 64 + n2 * 2 + 1] - rmax[m]) * rinv[m];
        uint32_t off = m * 128 + ((n2 * 4) ^ ((m & 7) * 16));
        *(__half2*)((char*)Ah + off) = __floats2half2_rn(v0, v1);
    }
    __syncthreads();

    // GEMM1: C1[c][m] = sum_n yfh[c][n] * Ah[m][n]; warp w owns c-strip w*16
    {
        float acc[8][4];
        #pragma unroll
        for (int ni = 0; ni < 8; ni++)
            #pragma unroll
            for (int q = 0; q < 4; q++) acc[ni][q] = 0.f;
        #pragma unroll
        for (int ks = 0; ks < 4; ks++) {
            uint32_t a[4];
            {
                int row = w * 16 + (lane & 15);
                uint32_t off = row * 128 + (((ks * 16 + (lane >> 4) * 8) * 2) ^ ((row & 7) * 16));
                LDSM_X4(a[0], a[1], a[2], a[3], FhB + off);
            }
            #pragma unroll
            for (int ni = 0; ni < 8; ni++) {
                int mr = ni * 8 + (lane & 7);
                uint32_t off = mr * 128 + (((ks * 16 + ((lane >> 3) & 1) * 8) * 2) ^ ((mr & 7) * 16));
                uint32_t b0, b1;
                LDSM_X2(b0, b1, AhB + off);
                uint32_t bf[2] = {b0, b1};
                mma16816(acc[ni], a, bf);
            }
        }
        int cr = w * 16 + (lane >> 2);
        #pragma unroll
        for (int ni = 0; ni < 8; ni++) {
            int mc = ni * 8 + (lane & 3) * 2;
            float2 r0 = *(const float2*)(xfb + cr * 64 + mc);
            float2 r1 = *(const float2*)(xfb + (cr + 8) * 64 + mc);
            *(__half2*)&d_menh[(size_t)(b * 256 + cr) * 4096 + e * 64 + mc] =
                __floats2half2_rn(leaky(acc[ni][0] + r0.x), leaky(acc[ni][1] + r0.y));
            *(__half2*)&d_menh[(size_t)(b * 256 + cr + 8) * 4096 + e * 64 + mc] =
                __floats2half2_rn(leaky(acc[ni][2] + r1.x), leaky(acc[ni][3] + r1.y));
        }
    }
    __syncthreads();   // done reading Ah + Fh

    // phase 3: A2h[n][m] = col softmax (half, swizzled); Fh <- xf halves
    for (int idx = t; idx < 2048; idx += 256) {
        int n = idx & 63, m2 = idx >> 6;  // consecutive threads -> consecutive n (coalesced loc reads)
        float v0 = __expf(loc[(m2 * 2) * 64 + n]     - cmax[n]) * cinv[n];
        float v1 = __expf(loc[(m2 * 2 + 1) * 64 + n] - cmax[n]) * cinv[n];
        uint32_t off = n * 128 + ((m2 * 4) ^ ((n & 7) * 16));
        *(__half2*)((char*)Ah + off) = __floats2half2_rn(v0, v1);
    }
    for (int idx = t; idx < 4096; idx += 256) {
        int c = idx >> 5, n2 = idx & 31;
        float2 f = *(const float2*)(xfb + c * 64 + n2 * 2);
        uint32_t off = c * 128 + ((n2 * 4) ^ ((c & 7) * 16));
        *(__half2*)((char*)Fh + off) = __floats2half2_rn(f.x, f.y);
    }
    __syncthreads();

    // GEMM2: C2[c][n] = sum_m xfh[c][m] * A2h[n][m]
    {
        float acc[8][4];
        #pragma unroll
        for (int ni = 0; ni < 8; ni++)
            #pragma unroll
            for (int q = 0; q < 4; q++) acc[ni][q] = 0.f;
        #pragma unroll
        for (int ks = 0; ks < 4; ks++) {
            uint32_t a[4];
            {
                int row = w * 16 + (lane & 15);
                uint32_t off = row * 128 + (((ks * 16 + (lane >> 4) * 8) * 2) ^ ((row & 7) * 16));
                LDSM_X4(a[0], a[1], a[2], a[3], FhB + off);
            }
            #pragma unroll
            for (int ni = 0; ni < 8; ni++) {
                int nr = ni * 8 + (lane & 7);
                uint32_t off = nr * 128 + (((ks * 16 + ((lane >> 3) & 1) * 8) * 2) ^ ((nr & 7) * 16));
                uint32_t b0, b1;
                LDSM_X2(b0, b1, AhB + off);
                uint32_t bf[2] = {b0, b1};
                mma16816(acc[ni], a, bf);
            }
        }
        int cr = w * 16 + (lane >> 2);
        #pragma unroll
        for (int ni = 0; ni < 8; ni++) {
            int nc = ni * 8 + (lane & 3) * 2;
            float2 r0 = *(const float2*)(yfb + cr * 64 + nc);
            float2 r1 = *(const float2*)(yfb + (cr + 8) * 64 + nc);
            *(__half2*)&d_menh[(size_t)(b * 256 + 128 + cr) * 4096 + e * 64 + nc] =
                __floats2half2_rn(leaky(acc[ni][0] + r0.x), leaky(acc[ni][1] + r0.y));
            *(__half2*)&d_menh[(size_t)(b * 256 + 136 + cr) * 4096 + e * 64 + nc] =
                __floats2half2_rn(leaky(acc[ni][2] + r1.x), leaky(acc[ni][3] + r1.y));
        }
    }
}

// ---------------- conv1 via mma.sync: [128,384]@[384,128tile]; pre_out converted inline ----------------
__global__ __launch_bounds__(256) void k_conv1_mma(const float* __restrict__ pre_out,
                                                   const float* __restrict__ b1) {
    __shared__ __align__(16) __half As[128 * PITCH];
    __shared__ __align__(16) __half Bs[128 * PITCH];
    int tid = threadIdx.x, lane = tid & 31, w = tid >> 5;
    int wm = w >> 2, wn = w & 3;
    int tile = blockIdx.x, b = blockIdx.y;
    int p0 = tile * 128;
    uint32_t smA = smem_to_u32(As), smB = smem_to_u32(Bs);
    const uint32_t* w32 = (const uint32_t*)d_w1h;
    float acc[4][4][4];
    #pragma unroll
    for (int mi = 0; mi < 4; mi++)
        #pragma unroll
        for (int ni = 0; ni < 4; ni++)
            #pragma unroll
            for (int q = 0; q < 4; q++) acc[mi][ni][q] = 0.f;

    for (int k0 = 0; k0 < 384; k0 += 64) {
        __syncthreads();
        for (int idx = tid; idx < 4096; idx += 256) {         // A [o][k]
            int row = idx >> 5, cp = idx & 31;
            *(uint32_t*)&As[row * PITCH + cp * 2] = w32[row * 192 + (k0 >> 1) + cp];
        }
        for (int idx = tid; idx < 4096; idx += 256) {         // B transpose -> [p][k]
            int kk = idx >> 6, pp = (idx & 63) * 2;
            int c = k0 + kk;
            uint32_t v;
            if (c < 256) {
                v = *(const uint32_t*)(d_menh + (size_t)(b * 256 + c) * 4096 + p0 + pp);
            } else {
                float2 f = *(const float2*)(pre_out + ((size_t)b * 128 + (c - 256)) * 4096 + p0 + pp);
                __half2 h = __floats2half2_rn(f.x, f.y);
                v = *(uint32_t*)&h;
            }
            ((unsigned short*)Bs)[pp * PITCH + kk]       = (unsigned short)v;
            ((unsigned short*)Bs)[(pp + 1) * PITCH + kk] = (unsigned short)(v >> 16);
        }
        __syncthreads();
        #pragma unroll
        for (int ks = 0; ks < 4; ks++) {
            uint32_t a[4][4], bf[4][2];
            #pragma unroll
            for (int mi = 0; mi < 4; mi++) {
                uint32_t ad = smA + ((wm * 64 + mi * 16 + (lane & 15)) * PITCH + ks * 16 + (lane >> 4) * 8) * 2;
                LDSM_X4(a[mi][0], a[mi][1], a[mi][2], a[mi][3], ad);
            }
            #pragma unroll
            for (int ni = 0; ni < 4; ni++) {
                uint32_t ad = smB + ((wn * 32 + ni * 8 + (lane & 7)) * PITCH + ks * 16 + ((lane >> 3) & 1) * 8) * 2;
                LDSM_X2(bf[ni][0], bf[ni][1], ad);
            }
            #pragma unroll
            for (int mi = 0; mi < 4; mi++)
                #pragma unroll
                for (int ni = 0; ni < 4; ni++) mma16816(acc[mi][ni], a[mi], bf[ni]);
        }
    }

    int mrow = lane >> 2, ncol = (lane & 3) * 2;
    #pragma unroll
    for (int mi = 0; mi < 4; mi++) {
        int o = wm * 64 + mi * 16 + mrow;
        float bb0 = b1[o], bb1 = b1[o + 8];
        #pragma unroll
        for (int ni = 0; ni < 4; ni++) {
            int p = p0 + wn * 32 + ni * 8 + ncol;
            __half* dst = d_hh + (size_t)(b * NC + o) * 4096 + p;
            *(__half2*)dst = __floats2half2_rn(leaky(acc[mi][ni][0] + bb0), leaky(acc[mi][ni][1] + bb0));
            *(__half2*)(dst + (size_t)8 * 4096) = __floats2half2_rn(leaky(acc[mi][ni][2] + bb1), leaky(acc[mi][ni][3] + bb1));
        }
    }
}

// ---------------- conv2 3x3 via mma.sync: 9 shifted GEMMs, K=1152 ----------------
__global__ __launch_bounds__(256) void k_conv2_mma(const float* __restrict__ b2,
                                                   float* __restrict__ out) {
    __shared__ __align__(16) __half As[128 * PITCH];
    __shared__ __align__(16) __half Bs[128 * PITCH];
    int tid = threadIdx.x, lane = tid & 31, w = tid >> 5;
    int wm = w >> 2, wn = w & 3;
    int tile = blockIdx.x, b = blockIdx.y;
    int p0 = tile * 128;
    uint32_t smA = smem_to_u32(As), smB = smem_to_u32(Bs);
    const uint32_t* w32 = (const uint32_t*)d_w2s;
    const unsigned short* hh = (const unsigned short*)d_hh;
    float acc[4][4][4];
    #pragma unroll
    for (int mi = 0; mi < 4; mi++)
        #pragma unroll
        for (int ni = 0; ni < 4; ni++)
            #pragma unroll
            for (int q = 0; q < 4; q++) acc[mi][ni][q] = 0.f;

    for (int it = 0; it < 18; it++) {
        int shift = it >> 1;
        int c0 = (it & 1) * 64;
        int r = shift / 3 - 1, s = shift % 3 - 1;
        __syncthreads();
        for (int idx = tid; idx < 4096; idx += 256) {
            int row = idx >> 5, cp = idx & 31;
            *(uint32_t*)&As[row * PITCH + cp * 2] = w32[shift * 8192 + row * 64 + (c0 >> 1) + cp];
        }
        for (int idx = tid; idx < 8192; idx += 256) {
            int cc = idx >> 7, p = idx & 127;
            int pix = p0 + p;
            int ii = (pix >> 6) + r;
            int jj = (pix & 63) + s;
            unsigned short v = 0;
            if ((unsigned)ii < 64u && (unsigned)jj < 64u)
                v = hh[((size_t)(b * NC + c0 + cc) << 12) + ii * 64 + jj];
            ((unsigned short*)Bs)[p * PITCH + cc] = v;
        }
        __syncthreads();
        #pragma unroll
        for (int ks = 0; ks < 4; ks++) {
            uint32_t a[4][4], bf[4][2];
            #pragma unroll
            for (int mi = 0; mi < 4; mi++) {
                uint32_t ad = smA + ((wm * 64 + mi * 16 + (lane & 15)) * PITCH + ks * 16 + (lane >> 4) * 8) * 2;
                LDSM_X4(a[mi][0], a[mi][1], a[mi][2], a[mi][3], ad);
            }
            #pragma unroll
            for (int ni = 0; ni < 4; ni++) {
                uint32_t ad = smB + ((wn * 32 + ni * 8 + (lane & 7)) * PITCH + ks * 16 + ((lane >> 3) & 1) * 8) * 2;
                LDSM_X2(bf[ni][0], bf[ni][1], ad);
            }
            #pragma unroll
            for (int mi = 0; mi < 4; mi++)
                #pragma unroll
                for (int ni = 0; ni < 4; ni++) mma16816(acc[mi][ni], a[mi], bf[ni]);
        }
    }

    int mrow = lane >> 2, ncol = (lane & 3) * 2;
    #pragma unroll
    for (int mi = 0; mi < 4; mi++) {
        int o = wm * 64 + mi * 16 + mrow;
        float bb0 = b2[o], bb1 = b2[o + 8];
        #pragma unroll
        for (int ni = 0; ni < 4; ni++) {
            int p = p0 + wn * 32 + ni * 8 + ncol;
            float* dst = out + (size_t)(b * NC + o) * 4096 + p;
            *(float2*)dst = make_float2(leaky(acc[mi][ni][0] + bb0), leaky(acc[mi][ni][1] + bb0));
            *(float2*)(dst + (size_t)8 * 4096) = make_float2(leaky(acc[mi][ni][2] + bb1), leaky(acc[mi][ni][3] + bb1));
        }
    }
}

// ---------------- scores + g ----------------
__global__ void k_scoresg(const float* __restrict__ men2rel, const float* __restrict__ score_w,
                          const int* __restrict__ edge_mat, const float* __restrict__ m_bias) {
    int i = blockIdx.x, b = blockIdx.y, j = threadIdx.x;
    __shared__ float sw[128];
    sw[j] = score_w[j]; sw[j + 64] = score_w[j + 64];
    __syncthreads();
    float s = 0.f;
    #pragma unroll 8
    for (int c = 0; c < NC; c++) s += sw[c] * men2rel[((b * NC + c) * 64 + i) * 64 + j];
    int idx = (b * NE + i) * NE + j;
    d_g[idx] = d_L[idx] + leaky(s) + d_eltype[edge_mat[idx]] + m_bias[idx];
}

// ---------------- x_lin / y_lin ----------------
__global__ __launch_bounds__(256) void k_lin(const float* __restrict__ x, const float* __restrict__ y,
                                             const float* __restrict__ xlw, const float* __restrict__ ylw) {
    __shared__ float wsm[64 * 129];
    int ihalf = blockIdx.x, b = blockIdx.y, z = blockIdx.z;
    const float* w  = z ? ylw : xlw;
    const float* in = z ? y : x;
    float* outp     = z ? d_ylin : d_xlin;
    int t = threadIdx.x;
    int i0b = ihalf * 64;
    for (int idx = t; idx < 64 * 128; idx += 256) {
        int ii = idx >> 7, j = idx & 127;
        wsm[ii * 129 + j] = w[(i0b + ii) * NCIN + j];
    }
    __syncthreads();
    int ig = t >> 4, mg = t & 15;
    int iL0 = ig * 4, m0 = mg * 4;
    float acc[4][4];
    #pragma unroll
    for (int u = 0; u < 4; u++)
        #pragma unroll
        for (int v = 0; v < 4; v++) acc[u][v] = 0.f;
    const float* inb = in + b * NCIN * NE;
    for (int j = 0; j < 128; j++) {
        float av[4], bv[4];
        #pragma unroll
        for (int u = 0; u < 4; u++) av[u] = wsm[(iL0 + u) * 129 + j];
        #pragma unroll
        for (int v = 0; v < 4; v++) bv[v] = inb[j * NE + m0 + v];
        #pragma unroll
        for (int u = 0; u < 4; u++)
            #pragma unroll
            for (int v = 0; v < 4; v++) acc[u][v] += av[u] * bv[v];
    }
    #pragma unroll
    for (int u = 0; u < 4; u++)
        #pragma unroll
        for (int v = 0; v < 4; v++)
            outp[(b * NE + m0 + v) * NCIN + i0b + iL0 + u] = acc[u][v];
}

// ---------------- final softmax + output GEMMs ----------------
__global__ __launch_bounds__(256) void k_final(const float* __restrict__ x, const float* __restrict__ y,
                                               float* __restrict__ out) {
    __shared__ float G[64 * 65];
    __shared__ float lin[64 * 65];
    int ihalf = blockIdx.x, b = blockIdx.y, z = blockIdx.z;
    int t = threadIdx.x;
    int i0b = ihalf * 64;
    const float* linsrc = z ? d_xlin : d_ylin;
    for (int idx = t; idx < 4096; idx += 256) {
        int n = idx >> 6, iL = idx & 63;
        lin[n * 65 + iL] = linsrc[(b * NE + n) * NCIN + i0b + iL];
    }
    if (t < 64) {
        int row = t;
        const float* gb = d_g + b * 4096;
        float mx = -1e30f;
        for (int k = 0; k < 64; k++) {
            float gv = z ? gb[k * 64 + row] : gb[row * 64 + k];
            G[row * 65 + k] = gv;
            mx = fmaxf(mx, gv);
        }
        float s = 0.f;
        for (int k = 0; k < 64; k++) { float ev = __expf(G[row * 65 + k] - mx); G[row * 65 + k] = ev; s += ev; }
        float inv = 1.f / s;
        for (int k = 0; k < 64; k++) G[row * 65 + k] *= inv;
    }
    __syncthreads();

    int ig = t >> 4, mg = t & 15;
    int iL0 = ig * 4, m0 = mg * 4;
    float acc[4][4];
    #pragma unroll
    for (int u = 0; u < 4; u++)
        #pragma unroll
        for (int v = 0; v < 4; v++) acc[u][v] = 0.f;
    for (int k = 0; k < 64; k++) {
        float av[4], bv[4];
        #pragma unroll
        for (int u = 0; u < 4; u++) av[u] = lin[k * 65 + iL0 + u];
        #pragma unroll
        for (int v = 0; v < 4; v++) bv[v] = G[(m0 + v) * 65 + k];
        #pragma unroll
        for (int u = 0; u < 4; u++)
            #pragma unroll
            for (int v = 0; v < 4; v++) acc[u][v] += av[u] * bv[v];
    }
    const float* resid = z ? y : x;
    float* outb = out + (z ? NB * NCIN * NE : 0);
    #pragma unroll
    for (int u = 0; u < 4; u++) {
        int i = i0b + iL0 + u;
        #pragma unroll
        for (int v = 0; v < 4; v++) {
            int m = m0 + v;
            outb[(b * NCIN + i) * NE + m] = acc[u][v] + resid[b * NCIN * NE + i * NE + m];
        }
    }
}

extern "C" void kernel_launch(void* const* d_in, const int* in_sizes, int n_in,
                              void* d_out, int out_size) {
    const float* x          = (const float*)d_in[0];
    const float* y          = (const float*)d_in[1];
    const float* m_bias     = (const float*)d_in[2];
    const int*   edge_mat   = (const int*)d_in[3];
    const float* p_bias     = (const float*)d_in[4];
    const int*   path_mat   = (const int*)d_in[5];
    const float* pre_out    = (const float*)d_in[6];
    const float* xc1_w      = (const float*)d_in[7];
    const float* yc1_w      = (const float*)d_in[8];
    const float* xc2_w      = (const float*)d_in[9];
    const float* xc2_b      = (const float*)d_in[10];
    const float* yc2_w      = (const float*)d_in[11];
    const float* yc2_b      = (const float*)d_in[12];
    const float* pconv_w    = (const float*)d_in[13];
    const float* econv_w    = (const float*)d_in[14];
    const float* conv1_w    = (const float*)d_in[15];
    const float* conv1_b    = (const float*)d_in[16];
    const float* conv2_w    = (const float*)d_in[17];
    const float* conv2_b    = (const float*)d_in[18];
    const float* score_w    = (const float*)d_in[19];
    const float* xlin_w     = (const float*)d_in[20];
    const float* ylin_w     = (const float*)d_in[21];
    const float* edge_table = (const float*)d_in[22];
    const float* path_table = (const float*)d_in[23];

    float* out = (float*)d_out;
    float* out_men2rel = out + 2 * NB * NCIN * NE;

    k_prep<<<1, 128>>>(path_table, pconv_w, edge_table, econv_w, xc1_w, yc1_w, xc2_w, yc2_w);
    k_w1h<<<192, 256>>>(conv1_w);
    k_w2s<<<576, 256>>>(conv2_w);
    { dim3 g(NC, NB, 2); k_xfyf<<<g, 64>>>(x, y, xc1_w, yc1_w); }
    k_selfL<<<NB, 128>>>(x, y, xc2_b, yc2_b);
    { dim3 g(NE, NB); k_attn<<<g, 256>>>(path_mat, p_bias); }
    { dim3 g(32, NB); k_conv1_mma<<<g, 256>>>(pre_out, conv1_b); }
    { dim3 g(32, NB); k_conv2_mma<<<g, 256>>>(conv2_b, out_men2rel); }
    { dim3 g(64, NB); k_scoresg<<<g, 64>>>(out_men2rel, score_w, edge_mat, m_bias); }
    { dim3 g(2, NB, 2); k_lin<<<g, 256>>>(x, y, xlin_w, ylin_w); }
    { dim3 g(2, NB, 2); k_final<<<g, 256>>>(x, y, out); }
}

// round 8
// speedup vs baseline: 2.8548x; 1.2252x over previous
#include <cuda_runtime.h>
#include <cuda_fp16.h>
#include <cstdint>

constexpr int NB = 8, NE = 64, NCIN = 128, NC = 128;

__device__ __forceinline__ float leaky(float v) { return v >= 0.f ? v : 0.1f * v; }

// ---------------- scratch (static device globals) ----------------
__device__ float  d_xf[NB * NC * NE];
__device__ float  d_yf[NB * NC * NE];
__device__ float  d_L[NB * NE * NE];
__device__ float  d_pltype[20];
__device__ float  d_eltype[10];
__device__ float  d_wx[NCIN];
__device__ float  d_wy[NCIN];
__device__ float  d_g[NB * NE * NE];
__device__ float  d_xlin[NB * NE * NCIN];
__device__ float  d_ylin[NB * NE * NCIN];
__device__ __half d_menh[NB * 4096 * 256];   // path_fea [b][pix][c]  (c contiguous)
__device__ __half d_hh[NB * 4096 * NC];      // conv1 out [b][pix][c]
__device__ __half d_w1h[NC * 384];           // conv1 weights half [o][k]
__device__ __half d_w2s[9 * NC * NC];        // conv2 weights [shift][o][c] half

__device__ __forceinline__ uint32_t smem_to_u32(const void* p) {
    uint32_t a;
    asm("{ .reg .u64 t; cvta.to.shared.u64 t, %1; cvt.u32.u64 %0, t; }" : "=r"(a) : "l"(p));
    return a;
}
#define LDSM_X4(r0, r1, r2, r3, addr) \
    asm volatile("ldmatrix.sync.aligned.m8n8.x4.shared.b16 {%0,%1,%2,%3}, [%4];" \
        : "=r"(r0), "=r"(r1), "=r"(r2), "=r"(r3) : "r"(addr))
#define LDSM_X2(r0, r1, addr) \
    asm volatile("ldmatrix.sync.aligned.m8n8.x2.shared.b16 {%0,%1}, [%2];" \
        : "=r"(r0), "=r"(r1) : "r"(addr))
__device__ __forceinline__ void mma16816(float* c, const uint32_t* a, const uint32_t* b) {
    asm volatile("mma.sync.aligned.m16n8k16.row.col.f32.f16.f16.f32 "
                 "{%0,%1,%2,%3}, {%4,%5,%6,%7}, {%8,%9}, {%0,%1,%2,%3};"
                 : "+f"(c[0]), "+f"(c[1]), "+f"(c[2]), "+f"(c[3])
                 : "r"(a[0]), "r"(a[1]), "r"(a[2]), "r"(a[3]), "r"(b[0]), "r"(b[1]));
}
constexpr int PITCH = 72;    // halfs; 144B rows, ldmatrix conflict-free
constexpr int TPITCH = 136;  // halfs; 272B rows, 16B-aligned staging pitch

// ---------------- merged init: w1h + w2s + per-type/fused-weight prep ----------------
__global__ void k_init(const float* __restrict__ w1, const float* __restrict__ w2,
                       const float* __restrict__ path_table, const float* __restrict__ pconv_w,
                       const float* __restrict__ edge_table, const float* __restrict__ econv_w,
                       const float* __restrict__ xc1_w, const float* __restrict__ yc1_w,
                       const float* __restrict__ xc2_w, const float* __restrict__ yc2_w) {
    int blk = blockIdx.x, t = threadIdx.x;
    if (blk < 192) {
        int i = blk * 256 + t;
        d_w1h[i] = __float2half(w1[i]);
    } else if (blk < 768) {
        int i = (blk - 192) * 256 + t;
        int shift = i / 16384, rem = i % 16384;
        int o = rem >> 7, c = rem & 127;
        d_w2s[i] = __float2half(w2[(o * NC + c) * 9 + shift]);
    } else {
        if (t < 20) {
            float s = 0.f;
            #pragma unroll
            for (int d = 0; d < 32; d++) s += path_table[t * 32 + d] * pconv_w[d];
            d_pltype[t] = leaky(s);
        }
        if (t < 10) {
            float s = 0.f;
            #pragma unroll
            for (int d = 0; d < 32; d++) s += edge_table[t * 32 + d] * econv_w[d];
            d_eltype[t] = leaky(s);
        }
        if (t < 128) {
            float ax = 0.f, ay = 0.f;
            #pragma unroll 8
            for (int c = 0; c < NC; c++) {
                ax += xc2_w[c] * xc1_w[c * NCIN + t];
                ay += yc2_w[c] * yc1_w[c * NCIN + t];
            }
            d_wx[t] = ax; d_wy[t] = ay;
        }
    }
}

// ---------------- x_f / y_f via mma.sync: [128,128]@[128,64] per (b,z) ----------------
__global__ __launch_bounds__(256) void k_xfyf(const float* __restrict__ x, const float* __restrict__ y,
                                              const float* __restrict__ xw, const float* __restrict__ yw) {
    __shared__ __align__(16) __half As[128 * PITCH];
    __shared__ __align__(16) __half Bs[64 * PITCH];
    int b = blockIdx.x, z = blockIdx.y;
    const float* w  = z ? yw : xw;
    const float* in = (z ? y : x) + b * NCIN * NE;
    float* outp     = (z ? d_yf : d_xf) + b * NC * NE;
    int tid = threadIdx.x, lane = tid & 31, wp = tid >> 5;
    int wm = wp >> 1, wn = wp & 1;
    uint32_t smA = smem_to_u32(As), smB = smem_to_u32(Bs);
    float acc[2][4][4];
    #pragma unroll
    for (int mi = 0; mi < 2; mi++)
        #pragma unroll
        for (int ni = 0; ni < 4; ni++)
            #pragma unroll
            for (int q = 0; q < 4; q++) acc[mi][ni][q] = 0.f;

    for (int k0 = 0; k0 < 128; k0 += 64) {
        __syncthreads();
        for (int idx = tid; idx < 4096; idx += 256) {       // A: w[c][k] fp32->half
            int c = idx >> 5, i2 = idx & 31;
            float2 f = *(const float2*)(w + c * 128 + k0 + i2 * 2);
            *(__half2*)&As[c * PITCH + i2 * 2] = __floats2half2_rn(f.x, f.y);
        }
        for (int idx = tid; idx < 2048; idx += 256) {       // B: x[i][m] -> Bs[m][i]
            int i = idx >> 5, m2 = idx & 31;
            float2 f = *(const float2*)(in + (k0 + i) * 64 + m2 * 2);
            Bs[(m2 * 2) * PITCH + i]     = __float2half(f.x);
            Bs[(m2 * 2 + 1) * PITCH + i] = __float2half(f.y);
        }
        __syncthreads();
        #pragma unroll
        for (int ks = 0; ks < 4; ks++) {
            uint32_t a[2][4], bf[4][2];
            #pragma unroll
            for (int mi = 0; mi < 2; mi++) {
                uint32_t ad = smA + ((wm * 32 + mi * 16 + (lane & 15)) * PITCH + ks * 16 + (lane >> 4) * 8) * 2;
                LDSM_X4(a[mi][0], a[mi][1], a[mi][2], a[mi][3], ad);
            }
            #pragma unroll
            for (int ni = 0; ni < 4; ni++) {
                uint32_t ad = smB + ((wn * 32 + ni * 8 + (lane & 7)) * PITCH + ks * 16 + ((lane >> 3) & 1) * 8) * 2;
                LDSM_X2(bf[ni][0], bf[ni][1], ad);
            }
            #pragma unroll
            for (int mi = 0; mi < 2; mi++)
                #pragma unroll
                for (int ni = 0; ni < 4; ni++) mma16816(acc[mi][ni], a[mi], bf[ni]);
        }
    }
    #pragma unroll
    for (int mi = 0; mi < 2; mi++) {
        int c = wm * 32 + mi * 16 + (lane >> 2);
        #pragma unroll
        for (int ni = 0; ni < 4; ni++) {
            int m = wn * 32 + ni * 8 + (lane & 3) * 2;
            *(float2*)(outp + c * 64 + m)       = make_float2(acc[mi][ni][0], acc[mi][ni][1]);
            *(float2*)(outp + (c + 8) * 64 + m) = make_float2(acc[mi][ni][2], acc[mi][ni][3]);
        }
    }
}

// ---------------- x_self / y_other / L ----------------
__global__ void k_selfL(const float* __restrict__ x, const float* __restrict__ y,
                        const float* __restrict__ xc2_b, const float* __restrict__ yc2_b) {
    int b = blockIdx.x, t = threadIdx.x;
    __shared__ float xs[NE], yo[NE];
    if (t < 64) {
        const float* xb = x + b * NCIN * NE + t;
        float a0 = 0.f, a1 = 0.f;
        #pragma unroll 8
        for (int i = 0; i < NCIN; i += 2) { a0 += d_wx[i] * xb[i * NE]; a1 += d_wx[i + 1] * xb[(i + 1) * NE]; }
        xs[t] = a0 + a1 + xc2_b[0];
    } else {
        int m = t - 64;
        const float* yb = y + b * NCIN * NE + m;
        float a0 = 0.f, a1 = 0.f;
        #pragma unroll 8
        for (int i = 0; i < NCIN; i += 2) { a0 += d_wy[i] * yb[i * NE]; a1 += d_wy[i + 1] * yb[(i + 1) * NE]; }
        yo[m] = a0 + a1 + yc2_b[0];
    }
    __syncthreads();
    for (int idx = t; idx < NE * NE; idx += 128) {
        int p = idx >> 6, q = idx & 63;
        d_L[b * NE * NE + idx] = leaky(xs[q] + yo[p]);
    }
}

// ---------------- per-(b,e) path attention: fp32 softmax + mma.sync, [pix][c] output ----------------
__global__ __launch_bounds__(256) void k_attn(const int* __restrict__ path_mat,
                                              const float* __restrict__ p_bias) {
    __shared__ __align__(16) float  loc[64 * 64];
    __shared__ __align__(16) __half Ah[64 * 64];
    __shared__ __align__(16) __half Fh[64 * TPITCH];   // feature tile (swizzled) / staging
    __shared__ float rmax[64], rinv[64], cmax[64], cinv[64];
    int e = blockIdx.x, b = blockIdx.y, t = threadIdx.x;
    int lane = t & 31, w = t >> 5;
    const int*   pm = path_mat + (b * NE + e) * 4096;
    const float* pb = p_bias  + (size_t)(b * NE + e) * 4096;
    const float* Lb = d_L + b * 4096;
    const float* xfb = d_xf + b * NC * NE;
    const float* yfb = d_yf + b * NC * NE;
    uint32_t AhB = smem_to_u32(Ah), FhB = smem_to_u32(Fh);
    __half* menb = d_menh + ((size_t)b * 4096 + e * 64) * 256;

    // phase 0: logits + stage yf as half (swizzled [c][n])
    for (int idx = t; idx < 4096; idx += 256)
        loc[idx] = Lb[idx] + d_pltype[pm[idx]] + pb[idx];
    for (int idx = t; idx < 4096; idx += 256) {
        int c = idx >> 5, n2 = idx & 31;
        float2 f = *(const float2*)(yfb + c * 64 + n2 * 2);
        uint32_t off = c * 128 + ((n2 * 4) ^ ((c & 7) * 16));
        *(__half2*)((char*)Fh + off) = __floats2half2_rn(f.x, f.y);
    }
    __syncthreads();

    // phase 1: row + col stats
    {
        int row = w * 8;
        #pragma unroll
        for (int rr = 0; rr < 8; rr++) {
            float v0 = loc[(row + rr) * 64 + lane];
            float v1 = loc[(row + rr) * 64 + 32 + lane];
            float mx = fmaxf(v0, v1);
            #pragma unroll
            for (int o = 16; o > 0; o >>= 1) mx = fmaxf(mx, __shfl_xor_sync(0xffffffff, mx, o));
            float s = __expf(v0 - mx) + __expf(v1 - mx);
            #pragma unroll
            for (int o = 16; o > 0; o >>= 1) s += __shfl_xor_sync(0xffffffff, s, o);
            if (lane == 0) { rmax[row + rr] = mx; rinv[row + rr] = 1.f / s; }
        }
    }
    if (t < 64) {
        float mx = -1e30f;
        for (int m = 0; m < 64; m++) mx = fmaxf(mx, loc[m * 64 + t]);
        float s = 0.f;
        for (int m = 0; m < 64; m++) s += __expf(loc[m * 64 + t] - mx);
        cmax[t] = mx; cinv[t] = 1.f / s;
    }
    __syncthreads();

    // phase 2: Ah[m][n] = row softmax
    for (int idx = t; idx < 2048; idx += 256) {
        int m = idx >> 5, n2 = idx & 31;
        float v0 = __expf(loc[m * 64 + n2 * 2]     - rmax[m]) * rinv[m];
        float v1 = __expf(loc[m * 64 + n2 * 2 + 1] - rmax[m]) * rinv[m];
        uint32_t off = m * 128 + ((n2 * 4) ^ ((m & 7) * 16));
        *(__half2*)((char*)Ah + off) = __floats2half2_rn(v0, v1);
    }
    __syncthreads();

    // GEMM1: C1[c][m] = sum_n yfh[c][n]*Ah[m][n]
    float acc[8][4];
    #pragma unroll
    for (int ni = 0; ni < 8; ni++)
        #pragma unroll
        for (int q = 0; q < 4; q++) acc[ni][q] = 0.f;
    #pragma unroll
    for (int ks = 0; ks < 4; ks++) {
        uint32_t a[4];
        int row = w * 16 + (lane & 15);
        uint32_t off = row * 128 + (((ks * 16 + (lane >> 4) * 8) * 2) ^ ((row & 7) * 16));
        LDSM_X4(a[0], a[1], a[2], a[3], FhB + off);
        #pragma unroll
        for (int ni = 0; ni < 8; ni++) {
            int mr = ni * 8 + (lane & 7);
            uint32_t offb = mr * 128 + (((ks * 16 + ((lane >> 3) & 1) * 8) * 2) ^ ((mr & 7) * 16));
            uint32_t b0, b1;
            LDSM_X2(b0, b1, AhB + offb);
            uint32_t bf[2] = {b0, b1};
            mma16816(acc[ni], a, bf);
        }
    }
    __syncthreads();   // all warps done reading Fh/Ah

    // stage x_ret -> Fh[m][c] (pitch 136), add residual + leaky
    {
        int cr = w * 16 + (lane >> 2);
        #pragma unroll
        for (int ni = 0; ni < 8; ni++) {
            int mc = ni * 8 + (lane & 3) * 2;
            float2 r0 = *(const float2*)(xfb + cr * 64 + mc);
            float2 r1 = *(const float2*)(xfb + (cr + 8) * 64 + mc);
            Fh[mc * TPITCH + cr]           = __float2half(leaky(acc[ni][0] + r0.x));
            Fh[(mc + 1) * TPITCH + cr]     = __float2half(leaky(acc[ni][1] + r0.y));
            Fh[mc * TPITCH + cr + 8]       = __float2half(leaky(acc[ni][2] + r1.x));
            Fh[(mc + 1) * TPITCH + cr + 8] = __float2half(leaky(acc[ni][3] + r1.y));
        }
    }
    __syncthreads();
    // copy out x_ret rows: 64 rows x 128 halfs = 1024 uint4
    for (int idx = t; idx < 1024; idx += 256) {
        int row = idx >> 4, q = idx & 15;
        *(uint4*)(menb + (size_t)row * 256 + q * 8) = *(uint4*)&Fh[row * TPITCH + q * 8];
    }
    __syncthreads();

    // phase 3: A2h[n][m] = col softmax; Fh <- xf swizzled
    for (int idx = t; idx < 2048; idx += 256) {
        int n = idx & 63, m2 = idx >> 6;
        float v0 = __expf(loc[(m2 * 2) * 64 + n]     - cmax[n]) * cinv[n];
        float v1 = __expf(loc[(m2 * 2 + 1) * 64 + n] - cmax[n]) * cinv[n];
        uint32_t off = n * 128 + ((m2 * 4) ^ ((n & 7) * 16));
        *(__half2*)((char*)Ah + off) = __floats2half2_rn(v0, v1);
    }
    for (int idx = t; idx < 4096; idx += 256) {
        int c = idx >> 5, n2 = idx & 31;
        float2 f = *(const float2*)(xfb + c * 64 + n2 * 2);
        uint32_t off = c * 128 + ((n2 * 4) ^ ((c & 7) * 16));
        *(__half2*)((char*)Fh + off) = __floats2half2_rn(f.x, f.y);
    }
    __syncthreads();

    // GEMM2: C2[c][n] = sum_m xfh[c][m]*A2h[n][m]
    #pragma unroll
    for (int ni = 0; ni < 8; ni++)
        #pragma unroll
        for (int q = 0; q < 4; q++) acc[ni][q] = 0.f;
    #pragma unroll
    for (int ks = 0; ks < 4; ks++) {
        uint32_t a[4];
        int row = w * 16 + (lane & 15);
        uint32_t off = row * 128 + (((ks * 16 + (lane >> 4) * 8) * 2) ^ ((row & 7) * 16));
        LDSM_X4(a[0], a[1], a[2], a[3], FhB + off);
        #pragma unroll
        for (int ni = 0; ni < 8; ni++) {
            int nr = ni * 8 + (lane & 7);
            uint32_t offb = nr * 128 + (((ks * 16 + ((lane >> 3) & 1) * 8) * 2) ^ ((nr & 7) * 16));
            uint32_t b0, b1;
            LDSM_X2(b0, b1, AhB + offb);
            uint32_t bf[2] = {b0, b1};
            mma16816(acc[ni], a, bf);
        }
    }
    __syncthreads();

    // stage y_ret -> Fh[n][c], copy to c offset 128
    {
        int cr = w * 16 + (lane >> 2);
        #pragma unroll
        for (int ni = 0; ni < 8; ni++) {
            int nc = ni * 8 + (lane & 3) * 2;
            float2 r0 = *(const float2*)(yfb + cr * 64 + nc);
            float2 r1 = *(const float2*)(yfb + (cr + 8) * 64 + nc);
            Fh[nc * TPITCH + cr]           = __float2half(leaky(acc[ni][0] + r0.x));
            Fh[(nc + 1) * TPITCH + cr]     = __float2half(leaky(acc[ni][1] + r0.y));
            Fh[nc * TPITCH + cr + 8]       = __float2half(leaky(acc[ni][2] + r1.x));
            Fh[(nc + 1) * TPITCH + cr + 8] = __float2half(leaky(acc[ni][3] + r1.y));
        }
    }
    __syncthreads();
    for (int idx = t; idx < 1024; idx += 256) {
        int row = idx >> 4, q = idx & 15;
        *(uint4*)(menb + (size_t)row * 256 + 128 + q * 8) = *(uint4*)&Fh[row * TPITCH + q * 8];
    }
}

// ---------------- conv1 via mma.sync: [128,384]@[384,128tile], output [pix][c] ----------------
__global__ __launch_bounds__(256) void k_conv1_mma(const float* __restrict__ pre_out,
                                                   const float* __restrict__ b1) {
    __shared__ __align__(16) char smem_buf[2 * 128 * PITCH * 2];   // As+Bs / Ts union (36.9KB)
    __half* As = (__half*)smem_buf;
    __half* Bs = (__half*)smem_buf + 128 * PITCH;
    __half* Ts = (__half*)smem_buf;            // 128*136 halfs = 34.8KB
    int tid = threadIdx.x, lane = tid & 31, w = tid >> 5;
    int wm = w >> 2, wn = w & 3;
    int tile = blockIdx.x, b = blockIdx.y;
    int p0 = tile * 128;
    uint32_t smA = smem_to_u32(As), smB = smem_to_u32(Bs);
    const uint32_t* w32 = (const uint32_t*)d_w1h;
    float acc[4][4][4];
    #pragma unroll
    for (int mi = 0; mi < 4; mi++)
        #pragma unroll
        for (int ni = 0; ni < 4; ni++)
            #pragma unroll
            for (int q = 0; q < 4; q++) acc[mi][ni][q] = 0.f;

    for (int k0 = 0; k0 < 384; k0 += 64) {
        __syncthreads();
        for (int idx = tid; idx < 4096; idx += 256) {         // A [o][k]
            int row = idx >> 5, cp = idx & 31;
            *(uint32_t*)&As[row * PITCH + cp * 2] = w32[row * 192 + (k0 >> 1) + cp];
        }
        if (k0 < 256) {                                        // B from [pix][c]: vectorized
            for (int idx = tid; idx < 1024; idx += 256) {
                int p = idx >> 3, q = idx & 7;
                uint4 v = *(const uint4*)(d_menh + ((size_t)b * 4096 + p0 + p) * 256 + k0 + q * 8);
                *(uint4*)&Bs[p * PITCH + q * 8] = v;
            }
        } else {                                               // B from pre_out fp32 [c][pix]: transpose
            for (int idx = tid; idx < 4096; idx += 256) {
                int kk = idx >> 6, pp = (idx & 63) * 2;
                float2 f = *(const float2*)(pre_out + ((size_t)b * 128 + (k0 - 256 + kk)) * 4096 + p0 + pp);
                Bs[pp * PITCH + kk]       = __float2half(f.x);
                Bs[(pp + 1) * PITCH + kk] = __float2half(f.y);
            }
        }
        __syncthreads();
        #pragma unroll
        for (int ks = 0; ks < 4; ks++) {
            uint32_t a[4][4], bf[4][2];
            #pragma unroll
            for (int mi = 0; mi < 4; mi++) {
                uint32_t ad = smA + ((wm * 64 + mi * 16 + (lane & 15)) * PITCH + ks * 16 + (lane >> 4) * 8) * 2;
                LDSM_X4(a[mi][0], a[mi][1], a[mi][2], a[mi][3], ad);
            }
            #pragma unroll
            for (int ni = 0; ni < 4; ni++) {
                uint32_t ad = smB + ((wn * 32 + ni * 8 + (lane & 7)) * PITCH + ks * 16 + ((lane >> 3) & 1) * 8) * 2;
                LDSM_X2(bf[ni][0], bf[ni][1], ad);
            }
            #pragma unroll
            for (int mi = 0; mi < 4; mi++)
                #pragma unroll
                for (int ni = 0; ni < 4; ni++) mma16816(acc[mi][ni], a[mi], bf[ni]);
        }
    }
    __syncthreads();

    // stage Ts[p][o] then coalesced store to d_hh [b][pix][c]
    int mrow = lane >> 2, ncol = (lane & 3) * 2;
    #pragma unroll
    for (int mi = 0; mi < 4; mi++) {
        int o = wm * 64 + mi * 16 + mrow;
        float bb0 = b1[o], bb1 = b1[o + 8];
        #pragma unroll
        for (int ni = 0; ni < 4; ni++) {
            int p = wn * 32 + ni * 8 + ncol;
            Ts[p * TPITCH + o]           = __float2half(leaky(acc[mi][ni][0] + bb0));
            Ts[(p + 1) * TPITCH + o]     = __float2half(leaky(acc[mi][ni][1] + bb0));
            Ts[p * TPITCH + o + 8]       = __float2half(leaky(acc[mi][ni][2] + bb1));
            Ts[(p + 1) * TPITCH + o + 8] = __float2half(leaky(acc[mi][ni][3] + bb1));
        }
    }
    __syncthreads();
    // 128 rows x 128 halfs = 2048 uint4
    for (int idx = tid; idx < 2048; idx += 256) {
        int row = idx >> 4, q = idx & 15;
        *(uint4*)(d_hh + ((size_t)b * 4096 + p0 + row) * 128 + q * 8) = *(uint4*)&Ts[row * TPITCH + q * 8];
    }
}

// ---------------- conv2 3x3 via mma.sync: 9 shifted GEMMs, vectorized gathers ----------------
__global__ __launch_bounds__(256) void k_conv2_mma(const float* __restrict__ b2,
                                                   float* __restrict__ out) {
    __shared__ __align__(16) __half As[128 * PITCH];
    __shared__ __align__(16) __half Bs[128 * PITCH];
    int tid = threadIdx.x, lane = tid & 31, w = tid >> 5;
    int wm = w >> 2, wn = w & 3;
    int tile = blockIdx.x, b = blockIdx.y;
    int p0 = tile * 128;
    uint32_t smA = smem_to_u32(As), smB = smem_to_u32(Bs);
    const uint32_t* w32 = (const uint32_t*)d_w2s;
    float acc[4][4][4];
    #pragma unroll
    for (int mi = 0; mi < 4; mi++)
        #pragma unroll
        for (int ni = 0; ni < 4; ni++)
            #pragma unroll
            for (int q = 0; q < 4; q++) acc[mi][ni][q] = 0.f;

    for (int it = 0; it < 18; it++) {
        int shift = it >> 1;
        int c0 = (it & 1) * 64;
        int r = shift / 3 - 1, s = shift % 3 - 1;
        __syncthreads();
        for (int idx = tid; idx < 4096; idx += 256) {          // A: w2s[shift][o][c0..+63]
            int row = idx >> 5, cp = idx & 31;
            *(uint32_t*)&As[row * PITCH + cp * 2] = w32[shift * 8192 + row * 64 + (c0 >> 1) + cp];
        }
        for (int idx = tid; idx < 1024; idx += 256) {          // B: shifted [pix][c] rows, uint4
            int p = idx >> 3, q = idx & 7;
            int pix = p0 + p;
            int ii = (pix >> 6) + r;
            int jj = (pix & 63) + s;
            uint4 v = make_uint4(0u, 0u, 0u, 0u);
            if ((unsigned)ii < 64u && (unsigned)jj < 64u)
                v = *(const uint4*)(d_hh + ((size_t)b * 4096 + ii * 64 + jj) * 128 + c0 + q * 8);
            *(uint4*)&Bs[p * PITCH + q * 8] = v;
        }
        __syncthreads();
        #pragma unroll
        for (int ks = 0; ks < 4; ks++) {
            uint32_t a[4][4], bf[4][2];
            #pragma unroll
            for (int mi = 0; mi < 4; mi++) {
                uint32_t ad = smA + ((wm * 64 + mi * 16 + (lane & 15)) * PITCH + ks * 16 + (lane >> 4) * 8) * 2;
                LDSM_X4(a[mi][0], a[mi][1], a[mi][2], a[mi][3], ad);
            }
            #pragma unroll
            for (int ni = 0; ni < 4; ni++) {
                uint32_t ad = smB + ((wn * 32 + ni * 8 + (lane & 7)) * PITCH + ks * 16 + ((lane >> 3) & 1) * 8) * 2;
                LDSM_X2(bf[ni][0], bf[ni][1], ad);
            }
            #pragma unroll
            for (int mi = 0; mi < 4; mi++)
                #pragma unroll
                for (int ni = 0; ni < 4; ni++) mma16816(acc[mi][ni], a[mi], bf[ni]);
        }
    }

    int mrow = lane >> 2, ncol = (lane & 3) * 2;
    #pragma unroll
    for (int mi = 0; mi < 4; mi++) {
        int o = wm * 64 + mi * 16 + mrow;
        float bb0 = b2[o], bb1 = b2[o + 8];
        #pragma unroll
        for (int ni = 0; ni < 4; ni++) {
            int p = p0 + wn * 32 + ni * 8 + ncol;
            float* dst = out + (size_t)(b * NC + o) * 4096 + p;
            *(float2*)dst = make_float2(leaky(acc[mi][ni][0] + bb0), leaky(acc[mi][ni][1] + bb0));
            *(float2*)(dst + (size_t)8 * 4096) = make_float2(leaky(acc[mi][ni][2] + bb1), leaky(acc[mi][ni][3] + bb1));
        }
    }
}

// ---------------- scores + g ----------------
__global__ void k_scoresg(const float* __restrict__ men2rel, const float* __restrict__ score_w,
                          const int* __restrict__ edge_mat, const float* __restrict__ m_bias) {
    int i = blockIdx.x, b = blockIdx.y, j = threadIdx.x;
    __shared__ float sw[128];
    sw[j] = score_w[j]; sw[j + 64] = score_w[j + 64];
    __syncthreads();
    float s = 0.f;
    #pragma unroll 8
    for (int c = 0; c < NC; c++) s += sw[c] * men2rel[((b * NC + c) * 64 + i) * 64 + j];
    int idx = (b * NE + i) * NE + j;
    d_g[idx] = d_L[idx] + leaky(s) + d_eltype[edge_mat[idx]] + m_bias[idx];
}

// ---------------- x_lin / y_lin ----------------
__global__ __launch_bounds__(256) void k_lin(const float* __restrict__ x, const float* __restrict__ y,
                                             const float* __restrict__ xlw, const float* __restrict__ ylw) {
    __shared__ float wsm[64 * 129];
    int ihalf = blockIdx.x, b = blockIdx.y, z = blockIdx.z;
    const float* w  = z ? ylw : xlw;
    const float* in = z ? y : x;
    float* outp     = z ? d_ylin : d_xlin;
    int t = threadIdx.x;
    int i0b = ihalf * 64;
    for (int idx = t; idx < 64 * 128; idx += 256) {
        int ii = idx >> 7, j = idx & 127;
        wsm[ii * 129 + j] = w[(i0b + ii) * NCIN + j];
    }
    __syncthreads();
    int ig = t >> 4, mg = t & 15;
    int iL0 = ig * 4, m0 = mg * 4;
    float acc[4][4];
    #pragma unroll
    for (int u = 0; u < 4; u++)
        #pragma unroll
        for (int v = 0; v < 4; v++) acc[u][v] = 0.f;
    const float* inb = in + b * NCIN * NE;
    for (int j = 0; j < 128; j++) {
        float av[4], bv[4];
        #pragma unroll
        for (int u = 0; u < 4; u++) av[u] = wsm[(iL0 + u) * 129 + j];
        #pragma unroll
        for (int v = 0; v < 4; v++) bv[v] = inb[j * NE + m0 + v];
        #pragma unroll
        for (int u = 0; u < 4; u++)
            #pragma unroll
            for (int v = 0; v < 4; v++) acc[u][v] += av[u] * bv[v];
    }
    #pragma unroll
    for (int u = 0; u < 4; u++)
        #pragma unroll
        for (int v = 0; v < 4; v++)
            outp[(b * NE + m0 + v) * NCIN + i0b + iL0 + u] = acc[u][v];
}

// ---------------- final softmax + output GEMMs ----------------
__global__ __launch_bounds__(256) void k_final(const float* __restrict__ x, const float* __restrict__ y,
                                               float* __restrict__ out) {
    __shared__ float G[64 * 65];
    __shared__ float lin[64 * 65];
    int ihalf = blockIdx.x, b = blockIdx.y, z = blockIdx.z;
    int t = threadIdx.x;
    int i0b = ihalf * 64;
    const float* linsrc = z ? d_xlin : d_ylin;
    for (int idx = t; idx < 4096; idx += 256) {
        int n = idx >> 6, iL = idx & 63;
        lin[n * 65 + iL] = linsrc[(b * NE + n) * NCIN + i0b + iL];
    }
    if (t < 64) {
        int row = t;
        const float* gb = d_g + b * 4096;
        float mx = -1e30f;
        for (int k = 0; k < 64; k++) {
            float gv = z ? gb[k * 64 + row] : gb[row * 64 + k];
            G[row * 65 + k] = gv;
            mx = fmaxf(mx, gv);
        }
        float s = 0.f;
        for (int k = 0; k < 64; k++) { float ev = __expf(G[row * 65 + k] - mx); G[row * 65 + k] = ev; s += ev; }
        float inv = 1.f / s;
        for (int k = 0; k < 64; k++) G[row * 65 + k] *= inv;
    }
    __syncthreads();

    int ig = t >> 4, mg = t & 15;
    int iL0 = ig * 4, m0 = mg * 4;
    float acc[4][4];
    #pragma unroll
    for (int u = 0; u < 4; u++)
        #pragma unroll
        for (int v = 0; v < 4; v++) acc[u][v] = 0.f;
    for (int k = 0; k < 64; k++) {
        float av[4], bv[4];
        #pragma unroll
        for (int u = 0; u < 4; u++) av[u] = lin[k * 65 + iL0 + u];
        #pragma unroll
        for (int v = 0; v < 4; v++) bv[v] = G[(m0 + v) * 65 + k];
        #pragma unroll
        for (int u = 0; u < 4; u++)
            #pragma unroll
            for (int v = 0; v < 4; v++) acc[u][v] += av[u] * bv[v];
    }
    const float* resid = z ? y : x;
    float* outb = out + (z ? NB * NCIN * NE : 0);
    #pragma unroll
    for (int u = 0; u < 4; u++) {
        int i = i0b + iL0 + u;
        #pragma unroll
        for (int v = 0; v < 4; v++) {
            int m = m0 + v;
            outb[(b * NCIN + i) * NE + m] = acc[u][v] + resid[b * NCIN * NE + i * NE + m];
        }
    }
}

extern "C" void kernel_launch(void* const* d_in, const int* in_sizes, int n_in,
                              void* d_out, int out_size) {
    const float* x          = (const float*)d_in[0];
    const float* y          = (const float*)d_in[1];
    const float* m_bias     = (const float*)d_in[2];
    const int*   edge_mat   = (const int*)d_in[3];
    const float* p_bias     = (const float*)d_in[4];
    const int*   path_mat   = (const int*)d_in[5];
    const float* pre_out    = (const float*)d_in[6];
    const float* xc1_w      = (const float*)d_in[7];
    const float* yc1_w      = (const float*)d_in[8];
    const float* xc2_w      = (const float*)d_in[9];
    const float* xc2_b      = (const float*)d_in[10];
    const float* yc2_w      = (const float*)d_in[11];
    const float* yc2_b      = (const float*)d_in[12];
    const float* pconv_w    = (const float*)d_in[13];
    const float* econv_w    = (const float*)d_in[14];
    const float* conv1_w    = (const float*)d_in[15];
    const float* conv1_b    = (const float*)d_in[16];
    const float* conv2_w    = (const float*)d_in[17];
    const float* conv2_b    = (const float*)d_in[18];
    const float* score_w    = (const float*)d_in[19];
    const float* xlin_w     = (const float*)d_in[20];
    const float* ylin_w     = (const float*)d_in[21];
    const float* edge_table = (const float*)d_in[22];
    const float* path_table = (const float*)d_in[23];

    float* out = (float*)d_out;
    float* out_men2rel = out + 2 * NB * NCIN * NE;

    k_init<<<769, 256>>>(conv1_w, conv2_w, path_table, pconv_w, edge_table, econv_w,
                         xc1_w, yc1_w, xc2_w, yc2_w);
    { dim3 g(NB, 2); k_xfyf<<<g, 256>>>(x, y, xc1_w, yc1_w); }
    k_selfL<<<NB, 128>>>(x, y, xc2_b, yc2_b);
    { dim3 g(NE, NB); k_attn<<<g, 256>>>(path_mat, p_bias); }
    { dim3 g(32, NB); k_conv1_mma<<<g, 256>>>(pre_out, conv1_b); }
    { dim3 g(32, NB); k_conv2_mma<<<g, 256>>>(conv2_b, out_men2rel); }
    { dim3 g(64, NB); k_scoresg<<<g, 64>>>(out_men2rel, score_w, edge_mat, m_bias); }
    { dim3 g(2, NB, 2); k_lin<<<g, 256>>>(x, y, xlin_w, ylin_w); }
    { dim3 g(2, NB, 2); k_final<<<g, 256>>>(x, y, out); }
}